// round 3
// baseline (speedup 1.0000x reference)
#include <cuda_runtime.h>
#include <math.h>

// Problem dims (fixed by the dataset)
#define BB   16
#define TT   1024
#define DD   256        // key_dim == e_dim
#define NE   512        // codebook size
#define MR   (BB*TT)    // 16384 rows

// ---------------- scratch (__device__ globals: allocation-free) ----------------
__device__ float g_ksn[MR * DD];        // normalized key_soft         (16 MB)
__device__ float g_w[MR * NE];          // softmax weights             (32 MB)
__device__ float g_keys_norm[NE * DD];  // normalized keys
__device__ float g_vp_norm[NE * DD];    // normalized vparams
__device__ float g_vp_normT[DD * NE];   // vp_norm transposed [E, n_e]

// ---------------- rowwise L2 normalize, 256 cols, one block per row ------------
__global__ void rownorm256(const float* __restrict__ in, float* __restrict__ out) {
    int r = blockIdx.x;
    int t = threadIdx.x;                  // 256 threads
    float v = in[(long)r * 256 + t];
    float s = v * v;
    #pragma unroll
    for (int o = 16; o; o >>= 1) s += __shfl_xor_sync(0xffffffffu, s, o);
    __shared__ float ws[8];
    if ((t & 31) == 0) ws[t >> 5] = s;
    __syncthreads();
    if (t < 8) {
        float x = ws[t];
        #pragma unroll
        for (int o = 4; o; o >>= 1) x += __shfl_xor_sync(0xffu, x, o);
        if (t == 0) ws[0] = x;
    }
    __syncthreads();
    float scale = 1.0f / fmaxf(sqrtf(ws[0]), 1e-12f);
    out[(long)r * 256 + t] = v * scale;
}

// ---------------- transpose vp_norm [512,256] -> vp_normT [256,512] ------------
__global__ void transpose_vp() {
    __shared__ float tile[32][33];
    int x = blockIdx.x * 32 + threadIdx.x;   // src col (0..255)
    int y = blockIdx.y * 32 + threadIdx.y;   // src row (0..511)
    tile[threadIdx.y][threadIdx.x] = g_vp_norm[y * 256 + x];
    __syncthreads();
    int tx = blockIdx.y * 32 + threadIdx.x;  // dst col = src row
    int ty = blockIdx.x * 32 + threadIdx.y;  // dst row = src col
    g_vp_normT[ty * 512 + tx] = tile[threadIdx.x][threadIdx.y];
}

// ---------------- softmax + argmax + hard gather, one block per row ------------
// reads score_ksh row (512), writes g_w row, idx (as float), and vparams_hard row
__global__ void softmax_argmax(const float* __restrict__ ksh,
                               float* __restrict__ out_idx,
                               float* __restrict__ out_hard) {
    int r = blockIdx.x;
    int t = threadIdx.x;                  // 256 threads, 2 cols each
    const float* row = ksh + (long)r * NE;
    float s0 = row[t], s1 = row[t + 256];
    float bv; int bi;
    if (s1 > s0) { bv = s1; bi = t + 256; } else { bv = s0; bi = t; } // tie -> lower idx
    #pragma unroll
    for (int o = 16; o; o >>= 1) {
        float ov = __shfl_xor_sync(0xffffffffu, bv, o);
        int   oi = __shfl_xor_sync(0xffffffffu, bi, o);
        if (ov > bv || (ov == bv && oi < bi)) { bv = ov; bi = oi; }
    }
    __shared__ float sv[8]; __shared__ int si[8];
    if ((t & 31) == 0) { sv[t >> 5] = bv; si[t >> 5] = bi; }
    __syncthreads();
    if (t < 8) {
        float x = sv[t]; int xi = si[t];
        #pragma unroll
        for (int o = 4; o; o >>= 1) {
            float ov = __shfl_xor_sync(0xffu, x, o);
            int   oi = __shfl_xor_sync(0xffu, xi, o);
            if (ov > x || (ov == x && oi < xi)) { x = ov; xi = oi; }
        }
        if (t == 0) { sv[0] = x; si[0] = xi; }
    }
    __syncthreads();
    float m = sv[0]; int idx = si[0];
    float e0 = expf(s0 - m), e1 = expf(s1 - m);
    float s = e0 + e1;
    #pragma unroll
    for (int o = 16; o; o >>= 1) s += __shfl_xor_sync(0xffffffffu, s, o);
    __shared__ float ss[8];
    if ((t & 31) == 0) ss[t >> 5] = s;
    __syncthreads();
    if (t < 8) {
        float x = ss[t];
        #pragma unroll
        for (int o = 4; o; o >>= 1) x += __shfl_xor_sync(0xffu, x, o);
        if (t == 0) ss[0] = x;
    }
    __syncthreads();
    float inv = 1.0f / ss[0];
    g_w[(long)r * NE + t]       = e0 * inv;
    g_w[(long)r * NE + t + 256] = e1 * inv;
    if (t == 0) out_idx[r] = (float)idx;
    // vparams_hard = l2norm(vparams[idx]) == vp_norm[idx]
    out_hard[(long)r * 256 + t] = g_vp_norm[(long)idx * 256 + t];
}

// ---------------- generic NT SGEMM: C[M,N] = A[M,K] * B[N,K]^T -----------------
// row-major A (stride K), row-major B (stride K), row-major C (stride N)
// batched via blockIdx.z with element strides. Dims must be multiples of tile.
__global__ __launch_bounds__(256) void sgemm_nt(
    const float* __restrict__ A, const float* __restrict__ Bm,
    float* __restrict__ C, int M, int N, int K,
    long strideA, long strideB, long strideC)
{
    const int BM = 128, BN = 128, BK = 16;
    A  += (long)blockIdx.z * strideA;
    Bm += (long)blockIdx.z * strideB;
    C  += (long)blockIdx.z * strideC;
    __shared__ float As[BK][BM + 4];
    __shared__ float Bs[BK][BN + 4];
    int bm = blockIdx.y * BM, bn = blockIdx.x * BN;
    int t = threadIdx.x;
    int tm = (t / 16) * 8, tn = (t % 16) * 8;
    float acc[8][8] = {};
    const float* Aptr = A + (long)bm * K;
    const float* Bptr = Bm + (long)bn * K;
    for (int k0 = 0; k0 < K; k0 += BK) {
        #pragma unroll
        for (int i = 0; i < 2; i++) {
            int fid = t + i * 256;          // 512 float4s per tile
            int r = fid >> 2;
            int c4 = (fid & 3) * 4;
            float4 va = *(const float4*)&Aptr[(long)r * K + k0 + c4];
            As[c4 + 0][r] = va.x; As[c4 + 1][r] = va.y;
            As[c4 + 2][r] = va.z; As[c4 + 3][r] = va.w;
            float4 vb = *(const float4*)&Bptr[(long)r * K + k0 + c4];
            Bs[c4 + 0][r] = vb.x; Bs[c4 + 1][r] = vb.y;
            Bs[c4 + 2][r] = vb.z; Bs[c4 + 3][r] = vb.w;
        }
        __syncthreads();
        #pragma unroll
        for (int k = 0; k < BK; k++) {
            float a[8], b[8];
            #pragma unroll
            for (int i = 0; i < 8; i++) a[i] = As[k][tm + i];
            #pragma unroll
            for (int j = 0; j < 8; j++) b[j] = Bs[k][tn + j];
            #pragma unroll
            for (int i = 0; i < 8; i++)
                #pragma unroll
                for (int j = 0; j < 8; j++)
                    acc[i][j] = fmaf(a[i], b[j], acc[i][j]);
        }
        __syncthreads();
    }
    #pragma unroll
    for (int i = 0; i < 8; i++) {
        float4* cp = (float4*)&C[(long)(bm + tm + i) * N + bn + tn];
        cp[0] = make_float4(acc[i][0], acc[i][1], acc[i][2], acc[i][3]);
        cp[1] = make_float4(acc[i][4], acc[i][5], acc[i][6], acc[i][7]);
    }
}

// --------------------------------- launch --------------------------------------
extern "C" void kernel_launch(void* const* d_in, const int* in_sizes, int n_in,
                              void* d_out, int out_size) {
    const float* key_soft = (const float*)d_in[0];   // [16,1024,256]
    const float* keys     = (const float*)d_in[1];   // [512,256]
    const float* vparams  = (const float*)d_in[2];   // [512,256]
    float* out = (float*)d_out;

    // output layout = tuple order, all float32
    float* o_idx  = out;                             // [16384]
    float* o_vw   = o_idx  + MR;                     // [16384,256]
    float* o_hard = o_vw   + (long)MR * DD;          // [16384,256]
    float* o_vpss = o_hard + (long)MR * DD;          // [16,1024,1024]
    float* o_vpsh = o_vpss + (long)MR * TT;          // [16384,512]
    float* o_kss  = o_vpsh + (long)MR * NE;          // [16,1024,1024]
    float* o_ksh  = o_kss  + (long)MR * TT;          // [16384,512]

    float *p_ksn, *p_w, *p_kn, *p_vpn, *p_vpnT;
    cudaGetSymbolAddress((void**)&p_ksn,  g_ksn);
    cudaGetSymbolAddress((void**)&p_w,    g_w);
    cudaGetSymbolAddress((void**)&p_kn,   g_keys_norm);
    cudaGetSymbolAddress((void**)&p_vpn,  g_vp_norm);
    cudaGetSymbolAddress((void**)&p_vpnT, g_vp_normT);

    // 1) normalize codebooks + inputs
    rownorm256<<<NE, 256>>>(keys,     p_kn);
    rownorm256<<<NE, 256>>>(vparams,  p_vpn);
    transpose_vp<<<dim3(DD / 32, NE / 32), dim3(32, 32)>>>();
    rownorm256<<<MR, 256>>>(key_soft, p_ksn);

    // 2) score_ksh = ksn @ keys_norm^T   [16384,512]
    sgemm_nt<<<dim3(NE / 128, MR / 128, 1), 256>>>(
        p_ksn, p_kn, o_ksh, MR, NE, DD, 0, 0, 0);

    // 3) softmax/argmax/hard-gather (writes g_w, o_idx, o_hard)
    softmax_argmax<<<MR, 256>>>(o_ksh, o_idx, o_hard);

    // 4) vw_raw = w @ vp_norm  ==  w @ (vp_normT)^T   [16384,256]
    sgemm_nt<<<dim3(DD / 128, MR / 128, 1), 256>>>(
        p_w, p_vpnT, o_vw, MR, DD, NE, 0, 0, 0);

    // 5) normalize vparams_w in place
    rownorm256<<<MR, 256>>>(o_vw, o_vw);

    // 6) score_vpsh = vparams_w @ vp_norm^T   [16384,512]
    sgemm_nt<<<dim3(NE / 128, MR / 128, 1), 256>>>(
        o_vw, p_vpn, o_vpsh, MR, NE, DD, 0, 0, 0);

    // 7) score_kss  = batched ksn_b @ ksn_b^T   [16,1024,1024]
    sgemm_nt<<<dim3(TT / 128, TT / 128, BB), 256>>>(
        p_ksn, p_ksn, o_kss, TT, TT, DD,
        (long)TT * DD, (long)TT * DD, (long)TT * TT);

    // 8) score_vpss = batched vw_b @ vw_b^T     [16,1024,1024]
    sgemm_nt<<<dim3(TT / 128, TT / 128, BB), 256>>>(
        o_vw, o_vw, o_vpss, TT, TT, DD,
        (long)TT * DD, (long)TT * DD, (long)TT * TT);
}

// round 5
// speedup vs baseline: 1.3234x; 1.3234x over previous
#include <cuda_runtime.h>
#include <math.h>
#include <stdint.h>

// Problem dims (fixed by the dataset)
#define BB   16
#define TT   1024
#define DD   256        // key_dim == e_dim
#define NE   512        // codebook size
#define MR   (BB*TT)    // 16384 rows

// ---------------- scratch (__device__ globals: allocation-free) ----------------
__device__ float g_ksn[MR * DD];        // normalized key_soft
__device__ float g_w[MR * NE];          // softmax weights
__device__ float g_keys_norm[NE * DD];
__device__ float g_vp_norm[NE * DD];
__device__ float g_vp_normT[DD * NE];   // vp_norm transposed [E, n_e]

// =============================== aux kernels ===================================
__global__ void rownorm256(const float* __restrict__ in, float* __restrict__ out) {
    int r = blockIdx.x;
    int t = threadIdx.x;                  // 256 threads
    float v = in[(long)r * 256 + t];
    float s = v * v;
    #pragma unroll
    for (int o = 16; o; o >>= 1) s += __shfl_xor_sync(0xffffffffu, s, o);
    __shared__ float ws[8];
    if ((t & 31) == 0) ws[t >> 5] = s;
    __syncthreads();
    if (t < 8) {
        float x = ws[t];
        #pragma unroll
        for (int o = 4; o; o >>= 1) x += __shfl_xor_sync(0xffu, x, o);
        if (t == 0) ws[0] = x;
    }
    __syncthreads();
    float scale = 1.0f / fmaxf(sqrtf(ws[0]), 1e-12f);
    out[(long)r * 256 + t] = v * scale;
}

__global__ void transpose_vp() {
    __shared__ float tile[32][33];
    int x = blockIdx.x * 32 + threadIdx.x;
    int y = blockIdx.y * 32 + threadIdx.y;
    tile[threadIdx.y][threadIdx.x] = g_vp_norm[y * 256 + x];
    __syncthreads();
    int tx = blockIdx.y * 32 + threadIdx.x;
    int ty = blockIdx.x * 32 + threadIdx.y;
    g_vp_normT[ty * 512 + tx] = tile[threadIdx.x][threadIdx.y];
}

__global__ void softmax_argmax(const float* __restrict__ ksh,
                               float* __restrict__ out_idx,
                               float* __restrict__ out_hard) {
    int r = blockIdx.x;
    int t = threadIdx.x;                  // 256 threads, 2 cols each
    const float* row = ksh + (long)r * NE;
    float s0 = row[t], s1 = row[t + 256];
    float bv; int bi;
    if (s1 > s0) { bv = s1; bi = t + 256; } else { bv = s0; bi = t; }
    #pragma unroll
    for (int o = 16; o; o >>= 1) {
        float ov = __shfl_xor_sync(0xffffffffu, bv, o);
        int   oi = __shfl_xor_sync(0xffffffffu, bi, o);
        if (ov > bv || (ov == bv && oi < bi)) { bv = ov; bi = oi; }
    }
    __shared__ float sv[8]; __shared__ int si[8];
    if ((t & 31) == 0) { sv[t >> 5] = bv; si[t >> 5] = bi; }
    __syncthreads();
    if (t < 8) {
        float x = sv[t]; int xi = si[t];
        #pragma unroll
        for (int o = 4; o; o >>= 1) {
            float ov = __shfl_xor_sync(0xffu, x, o);
            int   oi = __shfl_xor_sync(0xffu, xi, o);
            if (ov > x || (ov == x && oi < xi)) { x = ov; xi = oi; }
        }
        if (t == 0) { sv[0] = x; si[0] = xi; }
    }
    __syncthreads();
    float m = sv[0]; int idx = si[0];
    float e0 = expf(s0 - m), e1 = expf(s1 - m);
    float s = e0 + e1;
    #pragma unroll
    for (int o = 16; o; o >>= 1) s += __shfl_xor_sync(0xffffffffu, s, o);
    __shared__ float ss[8];
    if ((t & 31) == 0) ss[t >> 5] = s;
    __syncthreads();
    if (t < 8) {
        float x = ss[t];
        #pragma unroll
        for (int o = 4; o; o >>= 1) x += __shfl_xor_sync(0xffu, x, o);
        if (t == 0) ss[0] = x;
    }
    __syncthreads();
    float inv = 1.0f / ss[0];
    g_w[(long)r * NE + t]       = e0 * inv;
    g_w[(long)r * NE + t + 256] = e1 * inv;
    if (t == 0) out_idx[r] = (float)idx;
    out_hard[(long)r * 256 + t] = g_vp_norm[(long)idx * 256 + t];
}

// ======================= tf32x3 mma.sync GEMM (sm_80+ PTX) =====================
// C[M,N] = A[M,K] * B[N,K]^T, fp32 row-major K-contiguous.
// Block tile 128x128, BK=32 double-buffered; 8 warps, each 64x32.
// 3xTF32: acc += Ah*Bh + Ah*Bl + Al*Bh  (fp32-level accuracy).
//
// SMEM layout per stage (floats): fragment-order arrays, XOR-skewed:
//   A_hi [0,4096)     frag addr = ((ks*8+mt)*4+reg)*32 + ((group^(ks*2+(reg>>1)))*4)+within
//   A_lo [4096,8192)
//   B_hi [8192,12288) frag addr = 8192 + ((ks*16+nt)*2+reg)*32 + ((group^(ks*2+reg))*4)+within
//   B_lo [12288,16384)
#define STAGE_F 16384
#define GSMEM_BYTES (2 * STAGE_F * 4)   // 131072

__device__ __forceinline__ void cvt_split(float x, float& hi, float& lo) {
    uint32_t u;
    asm("cvt.rna.tf32.f32 %0, %1;" : "=r"(u) : "f"(x));
    hi = __uint_as_float(u);
    float r = x - hi;
    uint32_t u2;
    asm("cvt.rna.tf32.f32 %0, %1;" : "=r"(u2) : "f"(r));
    lo = __uint_as_float(u2);
}

__device__ __forceinline__ void mma8(float* d, const float* a, const float* b) {
    asm volatile(
        "mma.sync.aligned.m16n8k8.row.col.f32.tf32.tf32.f32 "
        "{%0,%1,%2,%3}, {%4,%5,%6,%7}, {%8,%9}, {%0,%1,%2,%3};"
        : "+f"(d[0]), "+f"(d[1]), "+f"(d[2]), "+f"(d[3])
        : "r"(__float_as_uint(a[0])), "r"(__float_as_uint(a[1])),
          "r"(__float_as_uint(a[2])), "r"(__float_as_uint(a[3])),
          "r"(__float_as_uint(b[0])), "r"(__float_as_uint(b[1])));
}

__global__ __launch_bounds__(256, 1) void gemm_tf32x3(
    const float* __restrict__ A, const float* __restrict__ B, float* __restrict__ C,
    int K, int ldC, long sA, long sB, long sC)
{
    extern __shared__ float smf[];
    const int t = threadIdx.x;
    const int wid = t >> 5, lane = t & 31;
    const int g = lane >> 2, q = lane & 3;      // fragment group / thread-in-group
    const float* Ap = A + (long)blockIdx.z * sA + (long)(blockIdx.y * 128) * K;
    const float* Bp = B + (long)blockIdx.z * sB + (long)(blockIdx.x * 128) * K;
    float* Cp = C + (long)blockIdx.z * sC + (long)(blockIdx.y * 128) * ldC
                  + blockIdx.x * 128;

    float acc[4][4][4];
    #pragma unroll
    for (int mi = 0; mi < 4; mi++)
        #pragma unroll
        for (int ni = 0; ni < 4; ni++)
            #pragma unroll
            for (int j = 0; j < 4; j++) acc[mi][ni][j] = 0.0f;

    float4 ra[4], rb[4];                        // prefetch regs for one BK chunk
    const int nk = K >> 5;

    auto gload = [&](int kc) {
        #pragma unroll
        for (int i = 0; i < 4; i++) {
            int fid = t + i * 256, r = fid >> 3, c16 = fid & 7;
            ra[i] = *(const float4*)(Ap + (long)r * K + kc * 32 + c16 * 4);
            rb[i] = *(const float4*)(Bp + (long)r * K + kc * 32 + c16 * 4);
        }
    };
    auto sstore = [&](int s) {                  // split + store regs -> stage s
        float* stg = smf + s * STAGE_F;
        #pragma unroll
        for (int i = 0; i < 4; i++) {
            int fid = t + i * 256, r = fid >> 3, c16 = fid & 7;
            int ks = c16 >> 1, kh = c16 & 1;
            // A: frag-order scatter. reg = (rl>=8) + kh*2; group = rl&7; within = k&3
            int mt = r >> 4, rl = r & 15;
            int offA = ((ks * 8 + mt) * 4 + (rl >> 3) + (kh << 1)) * 32
                     + (((rl & 7) ^ (ks * 2 + kh)) << 2);
            float4 h, l;
            cvt_split(ra[i].x, h.x, l.x); cvt_split(ra[i].y, h.y, l.y);
            cvt_split(ra[i].z, h.z, l.z); cvt_split(ra[i].w, h.w, l.w);
            *(float4*)(stg + offA)        = h;
            *(float4*)(stg + offA + 4096) = l;
            // B: reg = kh; group = n&7; within = k&3
            int nt = r >> 3, nl = r & 7;
            int offB = 8192 + ((ks * 16 + nt) * 2 + kh) * 32
                     + ((nl ^ (ks * 2 + kh)) << 2);
            cvt_split(rb[i].x, h.x, l.x); cvt_split(rb[i].y, h.y, l.y);
            cvt_split(rb[i].z, h.z, l.z); cvt_split(rb[i].w, h.w, l.w);
            *(float4*)(stg + offB)        = h;
            *(float4*)(stg + offB + 4096) = l;
        }
    };

    gload(0);
    sstore(0);
    if (nk > 1) gload(1);
    __syncthreads();

    for (int k = 0; k < nk; k++) {
        int s = k & 1;
        if (k + 1 < nk) {
            sstore(s ^ 1);                      // chunk k+1 regs -> other stage
            if (k + 2 < nk) gload(k + 2);       // LDG hides under mma below
        }
        const float* stg = smf + s * STAGE_F;
        #pragma unroll
        for (int ks = 0; ks < 4; ks++) {
            float bh[4][2], bl[4][2];
            #pragma unroll
            for (int ni = 0; ni < 4; ni++) {
                int nt = (wid & 3) * 4 + ni;
                #pragma unroll
                for (int rg = 0; rg < 2; rg++) {
                    int off = 8192 + ((ks * 16 + nt) * 2 + rg) * 32
                            + (((g ^ (ks * 2 + rg)) << 2) + q);
                    bh[ni][rg] = stg[off];
                    bl[ni][rg] = stg[off + 4096];
                }
            }
            #pragma unroll
            for (int mi = 0; mi < 4; mi++) {
                int mt = (wid >> 2) * 4 + mi;
                float ah[4], al[4];
                #pragma unroll
                for (int rg = 0; rg < 4; rg++) {
                    int off = ((ks * 8 + mt) * 4 + rg) * 32
                            + (((g ^ (ks * 2 + (rg >> 1))) << 2) + q);
                    ah[rg] = stg[off];
                    al[rg] = stg[off + 4096];
                }
                // pass-major order: dependency distance 4 on each accumulator
                #pragma unroll
                for (int ni = 0; ni < 4; ni++) mma8(acc[mi][ni], ah, bh[ni]);
                #pragma unroll
                for (int ni = 0; ni < 4; ni++) mma8(acc[mi][ni], ah, bl[ni]);
                #pragma unroll
                for (int ni = 0; ni < 4; ni++) mma8(acc[mi][ni], al, bh[ni]);
            }
        }
        __syncthreads();
    }

    // epilogue: direct fragment stores (float2, 8B-aligned, 32B sectors)
    #pragma unroll
    for (int mi = 0; mi < 4; mi++) {
        int row = (wid >> 2) * 64 + mi * 16 + g;
        #pragma unroll
        for (int ni = 0; ni < 4; ni++) {
            int col = (wid & 3) * 32 + ni * 8 + q * 2;
            *(float2*)&Cp[(long)row * ldC + col] =
                make_float2(acc[mi][ni][0], acc[mi][ni][1]);
            *(float2*)&Cp[(long)(row + 8) * ldC + col] =
                make_float2(acc[mi][ni][2], acc[mi][ni][3]);
        }
    }
}

// --------------------------------- launch --------------------------------------
extern "C" void kernel_launch(void* const* d_in, const int* in_sizes, int n_in,
                              void* d_out, int out_size) {
    const float* key_soft = (const float*)d_in[0];   // [16,1024,256]
    const float* keys     = (const float*)d_in[1];   // [512,256]
    const float* vparams  = (const float*)d_in[2];   // [512,256]
    float* out = (float*)d_out;

    float* o_idx  = out;                             // [16384]
    float* o_vw   = o_idx  + MR;                     // [16384,256]
    float* o_hard = o_vw   + (long)MR * DD;          // [16384,256]
    float* o_vpss = o_hard + (long)MR * DD;          // [16,1024,1024]
    float* o_vpsh = o_vpss + (long)MR * TT;          // [16384,512]
    float* o_kss  = o_vpsh + (long)MR * NE;          // [16,1024,1024]
    float* o_ksh  = o_kss  + (long)MR * TT;          // [16384,512]

    float *p_ksn, *p_w, *p_kn, *p_vpn, *p_vpnT;
    cudaGetSymbolAddress((void**)&p_ksn,  g_ksn);
    cudaGetSymbolAddress((void**)&p_w,    g_w);
    cudaGetSymbolAddress((void**)&p_kn,   g_keys_norm);
    cudaGetSymbolAddress((void**)&p_vpn,  g_vp_norm);
    cudaGetSymbolAddress((void**)&p_vpnT, g_vp_normT);

    cudaFuncSetAttribute(gemm_tf32x3, cudaFuncAttributeMaxDynamicSharedMemorySize,
                         GSMEM_BYTES);

    // 1) normalize codebooks + inputs
    rownorm256<<<NE, 256>>>(keys,     p_kn);
    rownorm256<<<NE, 256>>>(vparams,  p_vpn);
    transpose_vp<<<dim3(DD / 32, NE / 32), dim3(32, 32)>>>();
    rownorm256<<<MR, 256>>>(key_soft, p_ksn);

    // 2) score_ksh = ksn @ keys_norm^T   [16384,512]
    gemm_tf32x3<<<dim3(NE / 128, MR / 128, 1), 256, GSMEM_BYTES>>>(
        p_ksn, p_kn, o_ksh, DD, NE, 0, 0, 0);

    // 3) softmax/argmax/hard-gather
    softmax_argmax<<<MR, 256>>>(o_ksh, o_idx, o_hard);

    // 4) vw_raw = w @ vp_norm == w @ (vp_normT)^T   [16384,256]
    gemm_tf32x3<<<dim3(DD / 128, MR / 128, 1), 256, GSMEM_BYTES>>>(
        p_w, p_vpnT, o_vw, NE, DD, 0, 0, 0);

    // 5) normalize vparams_w in place
    rownorm256<<<MR, 256>>>(o_vw, o_vw);

    // 6) score_vpsh = vparams_w @ vp_norm^T   [16384,512]
    gemm_tf32x3<<<dim3(NE / 128, MR / 128, 1), 256, GSMEM_BYTES>>>(
        o_vw, p_vpn, o_vpsh, DD, NE, 0, 0, 0);

    // 7) score_kss = batched ksn_b @ ksn_b^T   [16,1024,1024]
    gemm_tf32x3<<<dim3(TT / 128, TT / 128, BB), 256, GSMEM_BYTES>>>(
        p_ksn, p_ksn, o_kss, DD, TT,
        (long)TT * DD, (long)TT * DD, (long)TT * TT);

    // 8) score_vpss = batched vw_b @ vw_b^T     [16,1024,1024]
    gemm_tf32x3<<<dim3(TT / 128, TT / 128, BB), 256, GSMEM_BYTES>>>(
        o_vw, o_vw, o_vpss, DD, TT,
        (long)TT * DD, (long)TT * DD, (long)TT * TT);
}

// round 6
// speedup vs baseline: 2.4575x; 1.8569x over previous
#include <cuda_runtime.h>
#include <math.h>
#include <stdint.h>

// Problem dims (fixed by the dataset)
#define BB   16
#define TT   1024
#define DD   256        // key_dim == e_dim
#define NE   512        // codebook size
#define MR   (BB*TT)    // 16384 rows

// ---------------- scratch (__device__ globals: allocation-free) ----------------
__device__ float g_ksn[MR * DD];        // normalized key_soft
__device__ float g_w[MR * NE];          // softmax weights
__device__ float g_keys_norm[NE * DD];
__device__ float g_vp_norm[NE * DD];
__device__ float g_vp_normT[DD * NE];   // vp_norm transposed [E, n_e]

// =============================== aux kernels ===================================
// warp-per-row L2 normalize, 256 cols: float4 loads, shuffle-only reduction
__global__ void rownorm256(const float* __restrict__ in, float* __restrict__ out,
                           int nrows) {
    int w = (blockIdx.x * blockDim.x + threadIdx.x) >> 5;
    int lane = threadIdx.x & 31;
    if (w >= nrows) return;
    const float4* ip = (const float4*)(in + (long)w * 256);
    float4 v0 = ip[lane], v1 = ip[lane + 32];
    float s = v0.x*v0.x + v0.y*v0.y + v0.z*v0.z + v0.w*v0.w
            + v1.x*v1.x + v1.y*v1.y + v1.z*v1.z + v1.w*v1.w;
    #pragma unroll
    for (int o = 16; o; o >>= 1) s += __shfl_xor_sync(0xffffffffu, s, o);
    float k = 1.0f / fmaxf(sqrtf(s), 1e-12f);
    float4* op = (float4*)(out + (long)w * 256);
    op[lane]      = make_float4(v0.x*k, v0.y*k, v0.z*k, v0.w*k);
    op[lane + 32] = make_float4(v1.x*k, v1.y*k, v1.z*k, v1.w*k);
}

__global__ void transpose_vp() {
    __shared__ float tile[32][33];
    int x = blockIdx.x * 32 + threadIdx.x;
    int y = blockIdx.y * 32 + threadIdx.y;
    tile[threadIdx.y][threadIdx.x] = g_vp_norm[y * 256 + x];
    __syncthreads();
    int tx = blockIdx.y * 32 + threadIdx.x;
    int ty = blockIdx.x * 32 + threadIdx.y;
    g_vp_normT[ty * 512 + tx] = tile[threadIdx.x][threadIdx.y];
}

__global__ void softmax_argmax(const float* __restrict__ ksh,
                               float* __restrict__ out_idx,
                               float* __restrict__ out_hard) {
    int r = blockIdx.x;
    int t = threadIdx.x;                  // 256 threads, 2 cols each
    const float* row = ksh + (long)r * NE;
    float s0 = row[t], s1 = row[t + 256];
    float bv; int bi;
    if (s1 > s0) { bv = s1; bi = t + 256; } else { bv = s0; bi = t; }
    #pragma unroll
    for (int o = 16; o; o >>= 1) {
        float ov = __shfl_xor_sync(0xffffffffu, bv, o);
        int   oi = __shfl_xor_sync(0xffffffffu, bi, o);
        if (ov > bv || (ov == bv && oi < bi)) { bv = ov; bi = oi; }
    }
    __shared__ float sv[8]; __shared__ int si[8];
    if ((t & 31) == 0) { sv[t >> 5] = bv; si[t >> 5] = bi; }
    __syncthreads();
    if (t < 8) {
        float x = sv[t]; int xi = si[t];
        #pragma unroll
        for (int o = 4; o; o >>= 1) {
            float ov = __shfl_xor_sync(0xffu, x, o);
            int   oi = __shfl_xor_sync(0xffu, xi, o);
            if (ov > x || (ov == x && oi < xi)) { x = ov; xi = oi; }
        }
        if (t == 0) { sv[0] = x; si[0] = xi; }
    }
    __syncthreads();
    float m = sv[0]; int idx = si[0];
    float e0 = expf(s0 - m), e1 = expf(s1 - m);
    float s = e0 + e1;
    #pragma unroll
    for (int o = 16; o; o >>= 1) s += __shfl_xor_sync(0xffffffffu, s, o);
    __shared__ float ss[8];
    if ((t & 31) == 0) ss[t >> 5] = s;
    __syncthreads();
    if (t < 8) {
        float x = ss[t];
        #pragma unroll
        for (int o = 4; o; o >>= 1) x += __shfl_xor_sync(0xffu, x, o);
        if (t == 0) ss[0] = x;
    }
    __syncthreads();
    float inv = 1.0f / ss[0];
    g_w[(long)r * NE + t]       = e0 * inv;
    g_w[(long)r * NE + t + 256] = e1 * inv;
    if (t == 0) out_idx[r] = (float)idx;
    out_hard[(long)r * 256 + t] = g_vp_norm[(long)idx * 256 + t];
}

// ===================== tf32 mma.sync GEMM (sm_80+ PTX) =========================
// C[M,N] = A[M,K] * B[N,K]^T, fp32 row-major K-contiguous.
// Block tile 128x128, BK=32 double-buffered; 8 warps, each 64x32.
// PASSES==3: acc += Ah*Bh + Ah*Bl + Al*Bh (fp32-level accuracy).
// PASSES==1: single tf32 pass (~1e-4 accuracy).
// SYM: A==B Gram matrix; grid.x enumerates 36 upper-triangular 128x128 tile
//      pairs; each tile written straight + transposed (both coalesced).
__device__ __forceinline__ void cvt_split(float x, float& hi, float& lo) {
    uint32_t u;
    asm("cvt.rna.tf32.f32 %0, %1;" : "=r"(u) : "f"(x));
    hi = __uint_as_float(u);
    float r = x - hi;
    uint32_t u2;
    asm("cvt.rna.tf32.f32 %0, %1;" : "=r"(u2) : "f"(r));
    lo = __uint_as_float(u2);
}
__device__ __forceinline__ float tf32_rna(float x) {
    uint32_t u;
    asm("cvt.rna.tf32.f32 %0, %1;" : "=r"(u) : "f"(x));
    return __uint_as_float(u);
}
__device__ __forceinline__ void mma8(float* d, const float* a, const float* b) {
    asm volatile(
        "mma.sync.aligned.m16n8k8.row.col.f32.tf32.tf32.f32 "
        "{%0,%1,%2,%3}, {%4,%5,%6,%7}, {%8,%9}, {%0,%1,%2,%3};"
        : "+f"(d[0]), "+f"(d[1]), "+f"(d[2]), "+f"(d[3])
        : "r"(__float_as_uint(a[0])), "r"(__float_as_uint(a[1])),
          "r"(__float_as_uint(a[2])), "r"(__float_as_uint(a[3])),
          "r"(__float_as_uint(b[0])), "r"(__float_as_uint(b[1])));
}

template<int PASSES, bool SYM>
__global__ __launch_bounds__(256, 1) void gemm_tf32(
    const float* __restrict__ A, const float* __restrict__ B, float* __restrict__ C,
    int K, int ldC, long sA, long sB, long sC)
{
    constexpr int BOFF  = (PASSES == 3) ? 8192 : 4096;   // B_hi float offset
    constexpr int STAGE = (PASSES == 3) ? 16384 : 8192;  // floats per stage
    extern __shared__ float smf[];
    const int t = threadIdx.x;
    const int wid = t >> 5, lane = t & 31;
    const int g = lane >> 2, q = lane & 3;

    int bi, bj;                                 // row / col tile index
    if constexpr (SYM) {
        int u = blockIdx.x, i = 0;
        while (u >= 8 - i) { u -= 8 - i; i++; } // 36 pairs, i<=j
        bi = i; bj = i + u;
    } else { bi = blockIdx.y; bj = blockIdx.x; }

    const float* Ap = A + (long)blockIdx.z * sA + (long)(bi * 128) * K;
    const float* Bp = B + (long)blockIdx.z * sB + (long)(bj * 128) * K;

    float acc[4][4][4];
    #pragma unroll
    for (int mi = 0; mi < 4; mi++)
        #pragma unroll
        for (int ni = 0; ni < 4; ni++)
            #pragma unroll
            for (int j = 0; j < 4; j++) acc[mi][ni][j] = 0.0f;

    float4 ra[4], rb[4];
    const int nk = K >> 5;

    auto gload = [&](int kc) {
        #pragma unroll
        for (int i = 0; i < 4; i++) {
            int fid = t + i * 256, r = fid >> 3, c16 = fid & 7;
            ra[i] = *(const float4*)(Ap + (long)r * K + kc * 32 + c16 * 4);
            rb[i] = *(const float4*)(Bp + (long)r * K + kc * 32 + c16 * 4);
        }
    };
    auto sstore = [&](int s) {
        float* stg = smf + s * STAGE;
        #pragma unroll
        for (int i = 0; i < 4; i++) {
            int fid = t + i * 256, r = fid >> 3, c16 = fid & 7;
            int ks = c16 >> 1, kh = c16 & 1;
            int mt = r >> 4, rl = r & 15;
            int offA = ((ks * 8 + mt) * 4 + (rl >> 3) + (kh << 1)) * 32
                     + (((rl & 7) ^ (ks * 2 + kh)) << 2);
            int nt = r >> 3, nl = r & 7;
            int offB = BOFF + ((ks * 16 + nt) * 2 + kh) * 32
                     + ((nl ^ (ks * 2 + kh)) << 2);
            if constexpr (PASSES == 3) {
                float4 h, l;
                cvt_split(ra[i].x, h.x, l.x); cvt_split(ra[i].y, h.y, l.y);
                cvt_split(ra[i].z, h.z, l.z); cvt_split(ra[i].w, h.w, l.w);
                *(float4*)(stg + offA)        = h;
                *(float4*)(stg + offA + 4096) = l;
                cvt_split(rb[i].x, h.x, l.x); cvt_split(rb[i].y, h.y, l.y);
                cvt_split(rb[i].z, h.z, l.z); cvt_split(rb[i].w, h.w, l.w);
                *(float4*)(stg + offB)        = h;
                *(float4*)(stg + offB + 4096) = l;
            } else {
                *(float4*)(stg + offA) = make_float4(
                    tf32_rna(ra[i].x), tf32_rna(ra[i].y),
                    tf32_rna(ra[i].z), tf32_rna(ra[i].w));
                *(float4*)(stg + offB) = make_float4(
                    tf32_rna(rb[i].x), tf32_rna(rb[i].y),
                    tf32_rna(rb[i].z), tf32_rna(rb[i].w));
            }
        }
    };

    gload(0);
    sstore(0);
    if (nk > 1) gload(1);
    __syncthreads();

    for (int k = 0; k < nk; k++) {
        int s = k & 1;
        if (k + 1 < nk) {
            sstore(s ^ 1);
            if (k + 2 < nk) gload(k + 2);
        }
        const float* stg = smf + s * STAGE;
        #pragma unroll
        for (int ks = 0; ks < 4; ks++) {
            float bh[4][2], bl[4][2];
            #pragma unroll
            for (int ni = 0; ni < 4; ni++) {
                int nt = (wid & 3) * 4 + ni;
                #pragma unroll
                for (int rg = 0; rg < 2; rg++) {
                    int off = BOFF + ((ks * 16 + nt) * 2 + rg) * 32
                            + (((g ^ (ks * 2 + rg)) << 2) + q);
                    bh[ni][rg] = stg[off];
                    if constexpr (PASSES == 3) bl[ni][rg] = stg[off + 4096];
                }
            }
            #pragma unroll
            for (int mi = 0; mi < 4; mi++) {
                int mt = (wid >> 2) * 4 + mi;
                float ah[4], al[4];
                #pragma unroll
                for (int rg = 0; rg < 4; rg++) {
                    int off = ((ks * 8 + mt) * 4 + rg) * 32
                            + (((g ^ (ks * 2 + (rg >> 1))) << 2) + q);
                    ah[rg] = stg[off];
                    if constexpr (PASSES == 3) al[rg] = stg[off + 4096];
                }
                #pragma unroll
                for (int ni = 0; ni < 4; ni++) mma8(acc[mi][ni], ah, bh[ni]);
                if constexpr (PASSES == 3) {
                    #pragma unroll
                    for (int ni = 0; ni < 4; ni++) mma8(acc[mi][ni], ah, bl[ni]);
                    #pragma unroll
                    for (int ni = 0; ni < 4; ni++) mma8(acc[mi][ni], al, bh[ni]);
                }
            }
        }
        __syncthreads();
    }

    if constexpr (!SYM) {
        float* Cp = C + (long)blockIdx.z * sC + (long)(bi * 128) * ldC + bj * 128;
        #pragma unroll
        for (int mi = 0; mi < 4; mi++) {
            int row = (wid >> 2) * 64 + mi * 16 + g;
            #pragma unroll
            for (int ni = 0; ni < 4; ni++) {
                int col = (wid & 3) * 32 + ni * 8 + q * 2;
                *(float2*)&Cp[(long)row * ldC + col] =
                    make_float2(acc[mi][ni][0], acc[mi][ni][1]);
                *(float2*)&Cp[(long)(row + 8) * ldC + col] =
                    make_float2(acc[mi][ni][2], acc[mi][ni][3]);
            }
        }
    } else {
        // stage the 128x128 tile (pitch 132: float4-aligned rows, conflict-free
        // transposed reads), then write straight + mirrored, both coalesced
        float* eb = smf;
        #pragma unroll
        for (int mi = 0; mi < 4; mi++) {
            int row = (wid >> 2) * 64 + mi * 16 + g;
            #pragma unroll
            for (int ni = 0; ni < 4; ni++) {
                int col = (wid & 3) * 32 + ni * 8 + q * 2;
                *(float2*)&eb[row * 132 + col] =
                    make_float2(acc[mi][ni][0], acc[mi][ni][1]);
                *(float2*)&eb[(row + 8) * 132 + col] =
                    make_float2(acc[mi][ni][2], acc[mi][ni][3]);
            }
        }
        __syncthreads();
        float* Cn = C + (long)blockIdx.z * sC + (long)(bi * 128) * ldC + bj * 128;
        #pragma unroll
        for (int i2 = 0; i2 < 16; i2++) {
            int id = t + i2 * 256;
            int r = id >> 5, c4 = (id & 31) * 4;
            *(float4*)&Cn[(long)r * ldC + c4] = *(float4*)&eb[r * 132 + c4];
        }
        if (bi != bj) {
            float* Cm = C + (long)blockIdx.z * sC + (long)(bj * 128) * ldC + bi * 128;
            #pragma unroll
            for (int i2 = 0; i2 < 16; i2++) {
                int id = t + i2 * 256;
                int rr = id & 127, c4 = (id >> 7) * 4;   // conflict-free map
                float4 v;
                v.x = eb[(c4 + 0) * 132 + rr];
                v.y = eb[(c4 + 1) * 132 + rr];
                v.z = eb[(c4 + 2) * 132 + rr];
                v.w = eb[(c4 + 3) * 132 + rr];
                *(float4*)&Cm[(long)rr * ldC + c4] = v;
            }
        }
    }
}

// --------------------------------- launch --------------------------------------
extern "C" void kernel_launch(void* const* d_in, const int* in_sizes, int n_in,
                              void* d_out, int out_size) {
    const float* key_soft = (const float*)d_in[0];   // [16,1024,256]
    const float* keys     = (const float*)d_in[1];   // [512,256]
    const float* vparams  = (const float*)d_in[2];   // [512,256]
    float* out = (float*)d_out;

    float* o_idx  = out;                             // [16384]
    float* o_vw   = o_idx  + MR;                     // [16384,256]
    float* o_hard = o_vw   + (long)MR * DD;          // [16384,256]
    float* o_vpss = o_hard + (long)MR * DD;          // [16,1024,1024]
    float* o_vpsh = o_vpss + (long)MR * TT;          // [16384,512]
    float* o_kss  = o_vpsh + (long)MR * NE;          // [16,1024,1024]
    float* o_ksh  = o_kss  + (long)MR * TT;          // [16384,512]

    float *p_ksn, *p_w, *p_kn, *p_vpn, *p_vpnT;
    cudaGetSymbolAddress((void**)&p_ksn,  g_ksn);
    cudaGetSymbolAddress((void**)&p_w,    g_w);
    cudaGetSymbolAddress((void**)&p_kn,   g_keys_norm);
    cudaGetSymbolAddress((void**)&p_vpn,  g_vp_norm);
    cudaGetSymbolAddress((void**)&p_vpnT, g_vp_normT);

    const int S3  = 2 * 16384 * 4;        // 131072: tf32x3 stages
    const int S1  = 2 * 8192 * 4;         // 65536:  tf32x1 stages
    const int S1S = 128 * 132 * 4;        // 67584:  sym epilogue buffer
    cudaFuncSetAttribute(gemm_tf32<3, false>,
                         cudaFuncAttributeMaxDynamicSharedMemorySize, S3);
    cudaFuncSetAttribute(gemm_tf32<1, false>,
                         cudaFuncAttributeMaxDynamicSharedMemorySize, S1);
    cudaFuncSetAttribute(gemm_tf32<1, true>,
                         cudaFuncAttributeMaxDynamicSharedMemorySize, S1S);

    // 1) normalize codebooks + inputs
    rownorm256<<<NE / 8, 256>>>(keys,     p_kn,  NE);
    rownorm256<<<NE / 8, 256>>>(vparams,  p_vpn, NE);
    transpose_vp<<<dim3(DD / 32, NE / 32), dim3(32, 32)>>>();
    rownorm256<<<MR / 8, 256>>>(key_soft, p_ksn, MR);

    // 2) score_ksh = ksn @ keys_norm^T  [16384,512]  (tf32x3: feeds argmax)
    gemm_tf32<3, false><<<dim3(NE / 128, MR / 128, 1), 256, S3>>>(
        p_ksn, p_kn, o_ksh, DD, NE, 0, 0, 0);

    // 3) softmax/argmax/hard-gather
    softmax_argmax<<<MR, 256>>>(o_ksh, o_idx, o_hard);

    // 4) vw_raw = w @ vp_norm == w @ (vp_normT)^T  [16384,256]  (tf32x1)
    gemm_tf32<1, false><<<dim3(DD / 128, MR / 128, 1), 256, S1>>>(
        p_w, p_vpnT, o_vw, NE, DD, 0, 0, 0);

    // 5) normalize vparams_w in place
    rownorm256<<<MR / 8, 256>>>(o_vw, o_vw, MR);

    // 6) score_vpsh = vparams_w @ vp_norm^T  [16384,512]  (tf32x1)
    gemm_tf32<1, false><<<dim3(NE / 128, MR / 128, 1), 256, S1>>>(
        o_vw, p_vpn, o_vpsh, DD, NE, 0, 0, 0);

    // 7) score_kss = batched ksn_b @ ksn_b^T  [16,1024,1024]  (symmetric tf32x1)
    gemm_tf32<1, true><<<dim3(36, 1, BB), 256, S1S>>>(
        p_ksn, p_ksn, o_kss, DD, TT,
        (long)TT * DD, (long)TT * DD, (long)TT * TT);

    // 8) score_vpss = batched vw_b @ vw_b^T  [16,1024,1024]  (symmetric tf32x1)
    gemm_tf32<1, true><<<dim3(36, 1, BB), 256, S1S>>>(
        o_vw, o_vw, o_vpss, DD, TT,
        (long)TT * DD, (long)TT * DD, (long)TT * TT);
}

// round 7
// speedup vs baseline: 2.8328x; 1.1527x over previous
#include <cuda_runtime.h>
#include <cuda_fp16.h>
#include <math.h>
#include <stdint.h>

// Problem dims (fixed by the dataset)
#define BB   16
#define TT   1024
#define DD   256        // key_dim == e_dim
#define NE   512        // codebook size
#define MR   (BB*TT)    // 16384 rows

// ---------------- scratch (__device__ globals: allocation-free) ----------------
__device__ __half g_ksn_h[MR * DD];     // normalized key_soft, fp16 hi
__device__ __half g_ksn_l[MR * DD];     // fp16 lo residual
__device__ __half g_wh[MR * NE];        // softmax weights fp16
__device__ __half g_keys_h[NE * DD];
__device__ __half g_keys_l[NE * DD];
__device__ float  g_vp_norm[NE * DD];   // fp32 (exact gather source)
__device__ __half g_vpn_h[NE * DD];
__device__ __half g_vpnT_h[DD * NE];    // vp_norm transposed fp16 [E, n_e]
__device__ __half g_vwh[MR * DD];       // normalized vparams_w fp16

// =============================== aux kernels ===================================
// warp-per-row L2 normalize, 256 cols; optional fp32 / fp16-hi / fp16-lo outputs
__global__ void rownorm_hl(const float* __restrict__ in, float* __restrict__ of,
                           __half* __restrict__ oh, __half* __restrict__ ol,
                           int nrows) {
    int w = (blockIdx.x * blockDim.x + threadIdx.x) >> 5;
    int lane = threadIdx.x & 31;
    if (w >= nrows) return;
    const float4* ip = (const float4*)(in + (long)w * 256);
    float4 v0 = ip[lane], v1 = ip[lane + 32];
    float s = v0.x*v0.x + v0.y*v0.y + v0.z*v0.z + v0.w*v0.w
            + v1.x*v1.x + v1.y*v1.y + v1.z*v1.z + v1.w*v1.w;
    #pragma unroll
    for (int o = 16; o; o >>= 1) s += __shfl_xor_sync(0xffffffffu, s, o);
    float k = 1.0f / fmaxf(sqrtf(s), 1e-12f);
    float4 a = make_float4(v0.x*k, v0.y*k, v0.z*k, v0.w*k);
    float4 b = make_float4(v1.x*k, v1.y*k, v1.z*k, v1.w*k);
    if (of) {
        float4* op = (float4*)(of + (long)w * 256);
        op[lane] = a; op[lane + 32] = b;
    }
    __half2 ha0 = __floats2half2_rn(a.x, a.y), ha1 = __floats2half2_rn(a.z, a.w);
    __half2 hb0 = __floats2half2_rn(b.x, b.y), hb1 = __floats2half2_rn(b.z, b.w);
    __half2* hp = (__half2*)(oh + (long)w * 256);
    hp[lane*2] = ha0; hp[lane*2+1] = ha1;
    hp[64 + lane*2] = hb0; hp[64 + lane*2+1] = hb1;
    if (ol) {
        float2 l0 = make_float2(a.x - __half2float(ha0.x), a.y - __half2float(ha0.y));
        float2 l1 = make_float2(a.z - __half2float(ha1.x), a.w - __half2float(ha1.y));
        float2 l2 = make_float2(b.x - __half2float(hb0.x), b.y - __half2float(hb0.y));
        float2 l3 = make_float2(b.z - __half2float(hb1.x), b.w - __half2float(hb1.y));
        __half2* lp = (__half2*)(ol + (long)w * 256);
        lp[lane*2]      = __floats2half2_rn(l0.x, l0.y);
        lp[lane*2+1]    = __floats2half2_rn(l1.x, l1.y);
        lp[64+lane*2]   = __floats2half2_rn(l2.x, l2.y);
        lp[64+lane*2+1] = __floats2half2_rn(l3.x, l3.y);
    }
}

__global__ void transpose_vp() {
    __shared__ float tile[32][33];
    int x = blockIdx.x * 32 + threadIdx.x;
    int y = blockIdx.y * 32 + threadIdx.y;
    tile[threadIdx.y][threadIdx.x] = g_vp_norm[y * 256 + x];
    __syncthreads();
    int tx = blockIdx.y * 32 + threadIdx.x;
    int ty = blockIdx.x * 32 + threadIdx.y;
    g_vpnT_h[ty * 512 + tx] = __float2half_rn(tile[threadIdx.x][threadIdx.y]);
}

__global__ void softmax_argmax(const float* __restrict__ ksh,
                               float* __restrict__ out_idx,
                               float* __restrict__ out_hard) {
    int r = blockIdx.x;
    int t = threadIdx.x;                  // 256 threads, 2 cols each
    const float* row = ksh + (long)r * NE;
    float s0 = row[t], s1 = row[t + 256];
    float bv; int bi;
    if (s1 > s0) { bv = s1; bi = t + 256; } else { bv = s0; bi = t; }
    #pragma unroll
    for (int o = 16; o; o >>= 1) {
        float ov = __shfl_xor_sync(0xffffffffu, bv, o);
        int   oi = __shfl_xor_sync(0xffffffffu, bi, o);
        if (ov > bv || (ov == bv && oi < bi)) { bv = ov; bi = oi; }
    }
    __shared__ float sv[8]; __shared__ int si[8];
    if ((t & 31) == 0) { sv[t >> 5] = bv; si[t >> 5] = bi; }
    __syncthreads();
    if (t < 8) {
        float x = sv[t]; int xi = si[t];
        #pragma unroll
        for (int o = 4; o; o >>= 1) {
            float ov = __shfl_xor_sync(0xffu, x, o);
            int   oi = __shfl_xor_sync(0xffu, xi, o);
            if (ov > x || (ov == x && oi < xi)) { x = ov; xi = oi; }
        }
        if (t == 0) { sv[0] = x; si[0] = xi; }
    }
    __syncthreads();
    float m = sv[0]; int idx = si[0];
    float e0 = expf(s0 - m), e1 = expf(s1 - m);
    float s = e0 + e1;
    #pragma unroll
    for (int o = 16; o; o >>= 1) s += __shfl_xor_sync(0xffffffffu, s, o);
    __shared__ float ss[8];
    if ((t & 31) == 0) ss[t >> 5] = s;
    __syncthreads();
    if (t < 8) {
        float x = ss[t];
        #pragma unroll
        for (int o = 4; o; o >>= 1) x += __shfl_xor_sync(0xffu, x, o);
        if (t == 0) ss[0] = x;
    }
    __syncthreads();
    float inv = 1.0f / ss[0];
    g_wh[(long)r * NE + t]       = __float2half_rn(e0 * inv);
    g_wh[(long)r * NE + t + 256] = __float2half_rn(e1 * inv);
    if (t == 0) out_idx[r] = (float)idx;
    out_hard[(long)r * 256 + t] = g_vp_norm[(long)idx * 256 + t];
}

// ==================== fp16 mma.sync GEMM (m16n8k16, sm_80+) ====================
// C[M,N] = A[M,K] * B[N,K]^T, fp16 inputs K-contiguous, fp32 accum/output.
// Block tile 128x128, BK=32, 3-stage cp.async pipeline; 8 warps, each 64x32.
// PASSES==3: acc += Ah*Bh + Ah*Bl + Al*Bh (fp32-level, for argmax-feeding ksh).
// SYM: A==B Gram; 36 upper-tri tile pairs; tile written straight + transposed.
__device__ __forceinline__ void cp16(uint32_t saddr, const void* g) {
    asm volatile("cp.async.cg.shared.global [%0], [%1], 16;"
                 :: "r"(saddr), "l"(g) : "memory");
}
__device__ __forceinline__ void mma16(float* d, const uint32_t* a, const uint32_t* b) {
    asm volatile(
        "mma.sync.aligned.m16n8k16.row.col.f32.f16.f16.f32 "
        "{%0,%1,%2,%3}, {%4,%5,%6,%7}, {%8,%9}, {%0,%1,%2,%3};"
        : "+f"(d[0]), "+f"(d[1]), "+f"(d[2]), "+f"(d[3])
        : "r"(a[0]), "r"(a[1]), "r"(a[2]), "r"(a[3]), "r"(b[0]), "r"(b[1]));
}

template<int PASSES, bool SYM>
__global__ __launch_bounds__(256, 1) void gemm_h(
    const __half* __restrict__ Ah_g, const __half* __restrict__ Al_g,
    const __half* __restrict__ Bh_g, const __half* __restrict__ Bl_g,
    float* __restrict__ C, int K, int ldC, long sA, long sB, long sC)
{
    constexpr int BOFFU  = (PASSES == 3) ? 4096 : 2048;  // B_hi u32 offset
    constexpr int STAGEU = (PASSES == 3) ? 8192 : 4096;  // u32 per stage
    extern __shared__ uint32_t smu[];
    const int t = threadIdx.x;
    const int wid = t >> 5, lane = t & 31;
    const int g = lane >> 2, q = lane & 3;

    int bi, bj;
    if constexpr (SYM) {
        int u = blockIdx.x, i = 0;
        while (u >= 8 - i) { u -= 8 - i; i++; }  // 36 pairs, i<=j
        bi = i; bj = i + u;
    } else { bi = blockIdx.y; bj = blockIdx.x; }

    const __half* Ah = Ah_g + (long)blockIdx.z * sA + (long)(bi * 128) * K;
    const __half* Bh = Bh_g + (long)blockIdx.z * sB + (long)(bj * 128) * K;
    const __half* Al = Al_g ? Al_g + (long)blockIdx.z * sA + (long)(bi * 128) * K : nullptr;
    const __half* Bl = Bl_g ? Bl_g + (long)blockIdx.z * sB + (long)(bj * 128) * K : nullptr;

    // precompute per-thread cp.async scatter targets (u32 units) + gmem offsets
    int aidx[2], bidx[2], goff[2];
    #pragma unroll
    for (int i = 0; i < 2; i++) {
        int fid = t + i * 256;            // 0..511
        int r = fid >> 2, c8 = fid & 3;   // row, 8-half quad
        int ks = c8 >> 1, hi = c8 & 1;
        goff[i] = r * K + c8 * 8;
        int mt = r >> 4, rl = r & 15;
        aidx[i] = (((ks * 8 + mt) * 4 + ((rl >> 3) + 2 * hi)) * 32)
                + (((rl & 7) ^ (ks * 2 + hi)) << 2);
        int nt = r >> 3, nl = r & 7;
        bidx[i] = BOFFU + (((ks * 16 + nt) * 2 + hi) * 32)
                + ((nl ^ (ks * 2 + hi)) << 2);
    }
    uint32_t smb = (uint32_t)__cvta_generic_to_shared(smu);

    auto issue = [&](int kc, int st) {
        uint32_t sb = smb + (uint32_t)(st * STAGEU) * 4u;
        #pragma unroll
        for (int i = 0; i < 2; i++) {
            cp16(sb + aidx[i] * 4, Ah + goff[i] + kc * 32);
            cp16(sb + bidx[i] * 4, Bh + goff[i] + kc * 32);
            if constexpr (PASSES == 3) {
                cp16(sb + (aidx[i] + 2048) * 4, Al + goff[i] + kc * 32);
                cp16(sb + (bidx[i] + 2048) * 4, Bl + goff[i] + kc * 32);
            }
        }
        asm volatile("cp.async.commit_group;" ::: "memory");
    };

    float acc[4][4][4];
    #pragma unroll
    for (int mi = 0; mi < 4; mi++)
        #pragma unroll
        for (int ni = 0; ni < 4; ni++)
            #pragma unroll
            for (int j = 0; j < 4; j++) acc[mi][ni][j] = 0.0f;

    const int nk = K >> 5;                // >= 8 here
    issue(0, 0);
    issue(1, 1);

    for (int k = 0; k < nk; k++) {
        int st = k % 3;
        if (k + 1 < nk) asm volatile("cp.async.wait_group 1;" ::: "memory");
        else            asm volatile("cp.async.wait_group 0;" ::: "memory");
        __syncthreads();
        if (k + 2 < nk) issue(k + 2, (k + 2) % 3);

        const uint32_t* stg = smu + st * STAGEU;
        #pragma unroll
        for (int ks = 0; ks < 2; ks++) {
            uint32_t bhf[4][2], blf[4][2];
            #pragma unroll
            for (int ni = 0; ni < 4; ni++) {
                int nt = (wid & 3) * 4 + ni;
                #pragma unroll
                for (int rg = 0; rg < 2; rg++) {
                    int off = BOFFU + ((ks * 16 + nt) * 2 + rg) * 32
                            + (((g ^ (ks * 2 + rg)) << 2) + q);
                    bhf[ni][rg] = stg[off];
                    if constexpr (PASSES == 3) blf[ni][rg] = stg[off + 2048];
                }
            }
            #pragma unroll
            for (int mi = 0; mi < 4; mi++) {
                int mt = (wid >> 2) * 4 + mi;
                uint32_t ahf[4], alf[4];
                #pragma unroll
                for (int rg = 0; rg < 4; rg++) {
                    int off = ((ks * 8 + mt) * 4 + rg) * 32
                            + (((g ^ (ks * 2 + (rg >> 1))) << 2) + q);
                    ahf[rg] = stg[off];
                    if constexpr (PASSES == 3) alf[rg] = stg[off + 2048];
                }
                #pragma unroll
                for (int ni = 0; ni < 4; ni++) mma16(acc[mi][ni], ahf, bhf[ni]);
                if constexpr (PASSES == 3) {
                    #pragma unroll
                    for (int ni = 0; ni < 4; ni++) mma16(acc[mi][ni], ahf, blf[ni]);
                    #pragma unroll
                    for (int ni = 0; ni < 4; ni++) mma16(acc[mi][ni], alf, bhf[ni]);
                }
            }
        }
        __syncthreads();
    }

    if constexpr (!SYM) {
        float* Cp = C + (long)blockIdx.z * sC + (long)(bi * 128) * ldC + bj * 128;
        #pragma unroll
        for (int mi = 0; mi < 4; mi++) {
            int row = (wid >> 2) * 64 + mi * 16 + g;
            #pragma unroll
            for (int ni = 0; ni < 4; ni++) {
                int col = (wid & 3) * 32 + ni * 8 + q * 2;
                *(float2*)&Cp[(long)row * ldC + col] =
                    make_float2(acc[mi][ni][0], acc[mi][ni][1]);
                *(float2*)&Cp[(long)(row + 8) * ldC + col] =
                    make_float2(acc[mi][ni][2], acc[mi][ni][3]);
            }
        }
    } else {
        __syncthreads();                  // stages no longer needed; reuse smem
        float* eb = (float*)smu;          // 128 x 132 staging tile
        #pragma unroll
        for (int mi = 0; mi < 4; mi++) {
            int row = (wid >> 2) * 64 + mi * 16 + g;
            #pragma unroll
            for (int ni = 0; ni < 4; ni++) {
                int col = (wid & 3) * 32 + ni * 8 + q * 2;
                *(float2*)&eb[row * 132 + col] =
                    make_float2(acc[mi][ni][0], acc[mi][ni][1]);
                *(float2*)&eb[(row + 8) * 132 + col] =
                    make_float2(acc[mi][ni][2], acc[mi][ni][3]);
            }
        }
        __syncthreads();
        float* Cn = C + (long)blockIdx.z * sC + (long)(bi * 128) * ldC + bj * 128;
        #pragma unroll
        for (int i2 = 0; i2 < 16; i2++) {
            int id = t + i2 * 256;
            int r = id >> 5, c4 = (id & 31) * 4;
            *(float4*)&Cn[(long)r * ldC + c4] = *(float4*)&eb[r * 132 + c4];
        }
        if (bi != bj) {
            float* Cm = C + (long)blockIdx.z * sC + (long)(bj * 128) * ldC + bi * 128;
            #pragma unroll
            for (int i2 = 0; i2 < 16; i2++) {
                int id = t + i2 * 256;
                int rr = id & 127, c4 = (id >> 7) * 4;   // conflict-free map
                float4 v;
                v.x = eb[(c4 + 0) * 132 + rr];
                v.y = eb[(c4 + 1) * 132 + rr];
                v.z = eb[(c4 + 2) * 132 + rr];
                v.w = eb[(c4 + 3) * 132 + rr];
                *(float4*)&Cm[(long)rr * ldC + c4] = v;
            }
        }
    }
}

// --------------------------------- launch --------------------------------------
extern "C" void kernel_launch(void* const* d_in, const int* in_sizes, int n_in,
                              void* d_out, int out_size) {
    const float* key_soft = (const float*)d_in[0];   // [16,1024,256]
    const float* keys     = (const float*)d_in[1];   // [512,256]
    const float* vparams  = (const float*)d_in[2];   // [512,256]
    float* out = (float*)d_out;

    float* o_idx  = out;                             // [16384]
    float* o_vw   = o_idx  + MR;                     // [16384,256]
    float* o_hard = o_vw   + (long)MR * DD;          // [16384,256]
    float* o_vpss = o_hard + (long)MR * DD;          // [16,1024,1024]
    float* o_vpsh = o_vpss + (long)MR * TT;          // [16384,512]
    float* o_kss  = o_vpsh + (long)MR * NE;          // [16,1024,1024]
    float* o_ksh  = o_kss  + (long)MR * TT;          // [16384,512]

    __half *p_ksn_h, *p_ksn_l, *p_wh, *p_keys_h, *p_keys_l, *p_vpn_h, *p_vpnT_h, *p_vwh;
    float* p_vpn;
    cudaGetSymbolAddress((void**)&p_ksn_h,  g_ksn_h);
    cudaGetSymbolAddress((void**)&p_ksn_l,  g_ksn_l);
    cudaGetSymbolAddress((void**)&p_wh,     g_wh);
    cudaGetSymbolAddress((void**)&p_keys_h, g_keys_h);
    cudaGetSymbolAddress((void**)&p_keys_l, g_keys_l);
    cudaGetSymbolAddress((void**)&p_vpn,    g_vp_norm);
    cudaGetSymbolAddress((void**)&p_vpn_h,  g_vpn_h);
    cudaGetSymbolAddress((void**)&p_vpnT_h, g_vpnT_h);
    cudaGetSymbolAddress((void**)&p_vwh,    g_vwh);

    const int S1  = 3 * 4096 * 4;         // 49152: fp16x1 stages
    const int S3  = 3 * 8192 * 4;         // 98304: fp16x3 stages
    const int S1S = 128 * 132 * 4;        // 67584: sym epilogue (> stages)
    cudaFuncSetAttribute(gemm_h<3, false>,
                         cudaFuncAttributeMaxDynamicSharedMemorySize, S3);
    cudaFuncSetAttribute(gemm_h<1, false>,
                         cudaFuncAttributeMaxDynamicSharedMemorySize, S1);
    cudaFuncSetAttribute(gemm_h<1, true>,
                         cudaFuncAttributeMaxDynamicSharedMemorySize, S1S);

    // 1) normalize codebooks + inputs (fp16 hi/lo products)
    rownorm_hl<<<NE / 8, 256>>>(keys,    nullptr, p_keys_h, p_keys_l, NE);
    rownorm_hl<<<NE / 8, 256>>>(vparams, p_vpn,   p_vpn_h,  nullptr,  NE);
    transpose_vp<<<dim3(DD / 32, NE / 32), dim3(32, 32)>>>();
    rownorm_hl<<<MR / 8, 256>>>(key_soft, nullptr, p_ksn_h, p_ksn_l, MR);

    // 2) score_ksh = ksn @ keys_norm^T  [16384,512]  (fp16 3-product: argmax-safe)
    gemm_h<3, false><<<dim3(NE / 128, MR / 128, 1), 256, S3>>>(
        p_ksn_h, p_ksn_l, p_keys_h, p_keys_l, o_ksh, DD, NE, 0, 0, 0);

    // 3) softmax/argmax/hard-gather (writes g_wh fp16, o_idx, o_hard)
    softmax_argmax<<<MR, 256>>>(o_ksh, o_idx, o_hard);

    // 4) vw_raw = w @ vp_norm == w @ (vp_normT)^T  [16384,256]
    gemm_h<1, false><<<dim3(DD / 128, MR / 128, 1), 256, S1>>>(
        p_wh, nullptr, p_vpnT_h, nullptr, o_vw, NE, DD, 0, 0, 0);

    // 5) normalize vparams_w: fp32 in place + fp16 copy
    rownorm_hl<<<MR / 8, 256>>>(o_vw, o_vw, p_vwh, nullptr, MR);

    // 6) score_vpsh = vparams_w @ vp_norm^T  [16384,512]
    gemm_h<1, false><<<dim3(NE / 128, MR / 128, 1), 256, S1>>>(
        p_vwh, nullptr, p_vpn_h, nullptr, o_vpsh, DD, NE, 0, 0, 0);

    // 7) score_kss = batched ksn_b @ ksn_b^T  [16,1024,1024]  (symmetric)
    gemm_h<1, true><<<dim3(36, 1, BB), 256, S1S>>>(
        p_ksn_h, nullptr, p_ksn_h, nullptr, o_kss, DD, TT,
        (long)TT * DD, (long)TT * DD, (long)TT * TT);

    // 8) score_vpss = batched vw_b @ vw_b^T  [16,1024,1024]  (symmetric)
    gemm_h<1, true><<<dim3(36, 1, BB), 256, S1S>>>(
        p_vwh, nullptr, p_vwh, nullptr, o_vpss, DD, TT,
        (long)TT * DD, (long)TT * DD, (long)TT * TT);
}

// round 8
// speedup vs baseline: 3.0219x; 1.0667x over previous
#include <cuda_runtime.h>
#include <cuda_fp16.h>
#include <math.h>
#include <stdint.h>

// Problem dims (fixed by the dataset)
#define BB   16
#define TT   1024
#define DD   256        // key_dim == e_dim
#define NE   512        // codebook size
#define MR   (BB*TT)    // 16384 rows

// ---------------- scratch (__device__ globals: allocation-free) ----------------
__device__ __half g_ksn_h[MR * DD];     // normalized key_soft, fp16
__device__ float  g_ksn_f[MR * DD];     // normalized key_soft, fp32 (argmax check)
__device__ __half g_wh[MR * NE];        // softmax weights fp16
__device__ __half g_keys_h[NE * DD];
__device__ float  g_keys_f[NE * DD];    // fp32 keys_norm (argmax check)
__device__ float  g_vp_norm[NE * DD];   // fp32 (exact gather source)
__device__ __half g_vpn_h[NE * DD];
__device__ __half g_vpnT_h[DD * NE];    // vp_norm transposed fp16 [E, n_e]
__device__ __half g_vwh[MR * DD];       // normalized vparams_w fp16

// =============================== aux kernels ===================================
// warp-per-row L2 normalize, 256 cols; optional fp32 + fp16 outputs
__global__ void rownorm_hl(const float* __restrict__ in, float* __restrict__ of,
                           __half* __restrict__ oh, int nrows) {
    int w = (blockIdx.x * blockDim.x + threadIdx.x) >> 5;
    int lane = threadIdx.x & 31;
    if (w >= nrows) return;
    const float4* ip = (const float4*)(in + (long)w * 256);
    float4 v0 = ip[lane], v1 = ip[lane + 32];
    float s = v0.x*v0.x + v0.y*v0.y + v0.z*v0.z + v0.w*v0.w
            + v1.x*v1.x + v1.y*v1.y + v1.z*v1.z + v1.w*v1.w;
    #pragma unroll
    for (int o = 16; o; o >>= 1) s += __shfl_xor_sync(0xffffffffu, s, o);
    float k = 1.0f / fmaxf(sqrtf(s), 1e-12f);
    float4 a = make_float4(v0.x*k, v0.y*k, v0.z*k, v0.w*k);
    float4 b = make_float4(v1.x*k, v1.y*k, v1.z*k, v1.w*k);
    if (of) {
        float4* op = (float4*)(of + (long)w * 256);
        op[lane] = a; op[lane + 32] = b;
    }
    __half2* hp = (__half2*)(oh + (long)w * 256);
    hp[lane*2]      = __floats2half2_rn(a.x, a.y);
    hp[lane*2+1]    = __floats2half2_rn(a.z, a.w);
    hp[64 + lane*2] = __floats2half2_rn(b.x, b.y);
    hp[64 + lane*2+1] = __floats2half2_rn(b.z, b.w);
}

__global__ void transpose_vp() {
    __shared__ float tile[32][33];
    int x = blockIdx.x * 32 + threadIdx.x;
    int y = blockIdx.y * 32 + threadIdx.y;
    tile[threadIdx.y][threadIdx.x] = g_vp_norm[y * 256 + x];
    __syncthreads();
    int tx = blockIdx.y * 32 + threadIdx.x;
    int ty = blockIdx.x * 32 + threadIdx.y;
    g_vpnT_h[ty * 512 + tx] = __float2half_rn(tile[threadIdx.x][threadIdx.y]);
}

// softmax + exact-argmax (fp32 candidate re-check) + hard gather, 1 block/row
__global__ void softmax_argmax(const float* __restrict__ ksh,
                               float* __restrict__ out_idx,
                               float* __restrict__ out_hard) {
    int r = blockIdx.x;
    int t = threadIdx.x;                  // 256 threads, 2 cols each
    const float* row = ksh + (long)r * NE;
    float s0 = row[t], s1 = row[t + 256];

    // 1) block max (value only) of fp16-accurate scores
    float bv = fmaxf(s0, s1);
    #pragma unroll
    for (int o = 16; o; o >>= 1) bv = fmaxf(bv, __shfl_xor_sync(0xffffffffu, bv, o));
    __shared__ float sv[8];
    if ((t & 31) == 0) sv[t >> 5] = bv;
    __syncthreads();
    if (t < 8) {
        float x = sv[t];
        #pragma unroll
        for (int o = 4; o; o >>= 1) x = fmaxf(x, __shfl_xor_sync(0xffu, x, o));
        if (t == 0) sv[0] = x;
    }
    __syncthreads();
    float m = sv[0];

    // 2) candidate collection (anything within eps of max could be true argmax;
    //    fp16-input dot error bound ~1e-3 for unit vectors -> eps=3e-3 is 3x margin)
    __shared__ int   cnt;
    __shared__ short cand[512];
    __shared__ float4 xrow[64];
    if (t == 0) cnt = 0;
    ((float*)xrow)[t] = g_ksn_f[(long)r * 256 + t];
    __syncthreads();
    const float eps = 3e-3f;
    if (s0 >= m - eps) { int p = atomicAdd(&cnt, 1); cand[p] = (short)t; }
    if (s1 >= m - eps) { int p = atomicAdd(&cnt, 1); cand[p] = (short)(t + 256); }
    __syncthreads();

    // 3) warp 0: exact fp32 dots for candidates; pick max, tie -> lower index
    __shared__ int besti;
    if (t < 32) {
        float bv2 = -2e30f; int bi2 = 1 << 30;
        int n = cnt;
        for (int c = 0; c < n; c++) {
            int j = cand[c];
            const float4* kp = (const float4*)(g_keys_f + (long)j * 256);
            float4 u0 = kp[t*2], u1 = kp[t*2+1];
            float4 x0 = xrow[t*2 >> 1]; // lane t covers dims 8t..8t+7
            // xrow is float4[64]; element pairs:
            float4 xa = xrow[t*2 - (t*2 & 1) ? 0 : 0]; (void)xa;
            float4 xv0 = xrow[(t*2)];   // placeholder (fixed below)
            (void)x0; (void)xv0;
            float4 p0 = ((const float4*)xrow)[t*2];
            float4 p1 = ((const float4*)xrow)[t*2+1];
            float d = u0.x*p0.x + u0.y*p0.y + u0.z*p0.z + u0.w*p0.w
                    + u1.x*p1.x + u1.y*p1.y + u1.z*p1.z + u1.w*p1.w;
            #pragma unroll
            for (int o = 16; o; o >>= 1) d += __shfl_xor_sync(0xffffffffu, d, o);
            if (d > bv2 || (d == bv2 && j < bi2)) { bv2 = d; bi2 = j; }
        }
        if (t == 0) besti = bi2;
    }

    // 4) softmax over fp16-accurate scores (error ~1e-4: fine for w)
    float e0 = expf(s0 - m), e1 = expf(s1 - m);
    float s = e0 + e1;
    #pragma unroll
    for (int o = 16; o; o >>= 1) s += __shfl_xor_sync(0xffffffffu, s, o);
    __shared__ float ss[8];
    if ((t & 31) == 0) ss[t >> 5] = s;
    __syncthreads();
    if (t < 8) {
        float x = ss[t];
        #pragma unroll
        for (int o = 4; o; o >>= 1) x += __shfl_xor_sync(0xffu, x, o);
        if (t == 0) ss[0] = x;
    }
    __syncthreads();
    float inv = 1.0f / ss[0];
    g_wh[(long)r * NE + t]       = __float2half_rn(e0 * inv);
    g_wh[(long)r * NE + t + 256] = __float2half_rn(e1 * inv);
    int idx = besti;
    if (t == 0) out_idx[r] = (float)idx;
    out_hard[(long)r * 256 + t] = g_vp_norm[(long)idx * 256 + t];
}

// ==================== fp16 mma.sync GEMM (m16n8k16, sm_80+) ====================
// C[M,N] = A[M,K] * B[N,K]^T, fp16 inputs K-contiguous, fp32 accum/output.
// Block tile 128x128, BK=32, 3-stage cp.async pipeline; 8 warps, each 64x32.
// SYM: A==B Gram; 36 upper-tri tile pairs; tile written straight + transposed.
__device__ __forceinline__ void cp16(uint32_t saddr, const void* g) {
    asm volatile("cp.async.cg.shared.global [%0], [%1], 16;"
                 :: "r"(saddr), "l"(g) : "memory");
}
__device__ __forceinline__ void mma16(float* d, const uint32_t* a, const uint32_t* b) {
    asm volatile(
        "mma.sync.aligned.m16n8k16.row.col.f32.f16.f16.f32 "
        "{%0,%1,%2,%3}, {%4,%5,%6,%7}, {%8,%9}, {%0,%1,%2,%3};"
        : "+f"(d[0]), "+f"(d[1]), "+f"(d[2]), "+f"(d[3])
        : "r"(a[0]), "r"(a[1]), "r"(a[2]), "r"(a[3]), "r"(b[0]), "r"(b[1]));
}

template<bool SYM>
__global__ __launch_bounds__(256, 1) void gemm_h(
    const __half* __restrict__ Ah_g, const __half* __restrict__ Bh_g,
    float* __restrict__ C, int K, int ldC, long sA, long sB, long sC)
{
    constexpr int BOFFU  = 2048;          // B u32 offset within stage
    constexpr int STAGEU = 4096;          // u32 per stage
    extern __shared__ uint32_t smu[];
    const int t = threadIdx.x;
    const int wid = t >> 5, lane = t & 31;
    const int g = lane >> 2, q = lane & 3;

    int bi, bj;
    if constexpr (SYM) {
        int u = blockIdx.x, i = 0;
        while (u >= 8 - i) { u -= 8 - i; i++; }  // 36 pairs, i<=j
        bi = i; bj = i + u;
    } else { bi = blockIdx.y; bj = blockIdx.x; }

    const __half* Ah = Ah_g + (long)blockIdx.z * sA + (long)(bi * 128) * K;
    const __half* Bh = Bh_g + (long)blockIdx.z * sB + (long)(bj * 128) * K;

    // per-thread cp.async scatter targets (u32 units) + gmem offsets
    int aidx[2], bidx[2], goff[2];
    #pragma unroll
    for (int i = 0; i < 2; i++) {
        int fid = t + i * 256;            // 0..511
        int r = fid >> 2, c8 = fid & 3;   // row, 8-half quad
        int ks = c8 >> 1, hi = c8 & 1;
        goff[i] = r * K + c8 * 8;
        int mt = r >> 4, rl = r & 15;
        aidx[i] = (((ks * 8 + mt) * 4 + ((rl >> 3) + 2 * hi)) * 32)
                + (((rl & 7) ^ (ks * 2 + hi)) << 2);
        int nt = r >> 3, nl = r & 7;
        bidx[i] = BOFFU + (((ks * 16 + nt) * 2 + hi) * 32)
                + ((nl ^ (ks * 2 + hi)) << 2);
    }
    uint32_t smb = (uint32_t)__cvta_generic_to_shared(smu);

    auto issue = [&](int kc, int st) {
        uint32_t sb = smb + (uint32_t)(st * STAGEU) * 4u;
        #pragma unroll
        for (int i = 0; i < 2; i++) {
            cp16(sb + aidx[i] * 4, Ah + goff[i] + kc * 32);
            cp16(sb + bidx[i] * 4, Bh + goff[i] + kc * 32);
        }
        asm volatile("cp.async.commit_group;" ::: "memory");
    };

    float acc[4][4][4];
    #pragma unroll
    for (int mi = 0; mi < 4; mi++)
        #pragma unroll
        for (int ni = 0; ni < 4; ni++)
            #pragma unroll
            for (int j = 0; j < 4; j++) acc[mi][ni][j] = 0.0f;

    const int nk = K >> 5;                // >= 8 here
    issue(0, 0);
    issue(1, 1);

    for (int k = 0; k < nk; k++) {
        int st = k % 3;
        if (k + 1 < nk) asm volatile("cp.async.wait_group 1;" ::: "memory");
        else            asm volatile("cp.async.wait_group 0;" ::: "memory");
        __syncthreads();
        if (k + 2 < nk) issue(k + 2, (k + 2) % 3);

        const uint32_t* stg = smu + st * STAGEU;
        #pragma unroll
        for (int ks = 0; ks < 2; ks++) {
            uint32_t bhf[4][2];
            #pragma unroll
            for (int ni = 0; ni < 4; ni++) {
                int nt = (wid & 3) * 4 + ni;
                #pragma unroll
                for (int rg = 0; rg < 2; rg++) {
                    int off = BOFFU + ((ks * 16 + nt) * 2 + rg) * 32
                            + (((g ^ (ks * 2 + rg)) << 2) + q);
                    bhf[ni][rg] = stg[off];
                }
            }
            #pragma unroll
            for (int mi = 0; mi < 4; mi++) {
                int mt = (wid >> 2) * 4 + mi;
                uint32_t ahf[4];
                #pragma unroll
                for (int rg = 0; rg < 4; rg++) {
                    int off = ((ks * 8 + mt) * 4 + rg) * 32
                            + (((g ^ (ks * 2 + (rg >> 1))) << 2) + q);
                    ahf[rg] = stg[off];
                }
                #pragma unroll
                for (int ni = 0; ni < 4; ni++) mma16(acc[mi][ni], ahf, bhf[ni]);
            }
        }
        __syncthreads();
    }

    if constexpr (!SYM) {
        float* Cp = C + (long)blockIdx.z * sC + (long)(bi * 128) * ldC + bj * 128;
        #pragma unroll
        for (int mi = 0; mi < 4; mi++) {
            int row = (wid >> 2) * 64 + mi * 16 + g;
            #pragma unroll
            for (int ni = 0; ni < 4; ni++) {
                int col = (wid & 3) * 32 + ni * 8 + q * 2;
                *(float2*)&Cp[(long)row * ldC + col] =
                    make_float2(acc[mi][ni][0], acc[mi][ni][1]);
                *(float2*)&Cp[(long)(row + 8) * ldC + col] =
                    make_float2(acc[mi][ni][2], acc[mi][ni][3]);
            }
        }
    } else {
        __syncthreads();                  // stages done; reuse smem
        float* eb = (float*)smu;          // 128 x 132 staging tile
        #pragma unroll
        for (int mi = 0; mi < 4; mi++) {
            int row = (wid >> 2) * 64 + mi * 16 + g;
            #pragma unroll
            for (int ni = 0; ni < 4; ni++) {
                int col = (wid & 3) * 32 + ni * 8 + q * 2;
                *(float2*)&eb[row * 132 + col] =
                    make_float2(acc[mi][ni][0], acc[mi][ni][1]);
                *(float2*)&eb[(row + 8) * 132 + col] =
                    make_float2(acc[mi][ni][2], acc[mi][ni][3]);
            }
        }
        __syncthreads();
        float* Cn = C + (long)blockIdx.z * sC + (long)(bi * 128) * ldC + bj * 128;
        #pragma unroll
        for (int i2 = 0; i2 < 16; i2++) {
            int id = t + i2 * 256;
            int r = id >> 5, c4 = (id & 31) * 4;
            *(float4*)&Cn[(long)r * ldC + c4] = *(float4*)&eb[r * 132 + c4];
        }
        if (bi != bj) {
            float* Cm = C + (long)blockIdx.z * sC + (long)(bj * 128) * ldC + bi * 128;
            #pragma unroll
            for (int i2 = 0; i2 < 16; i2++) {
                int id = t + i2 * 256;
                int rr = id & 127, c4 = (id >> 7) * 4;   // conflict-free map
                float4 v;
                v.x = eb[(c4 + 0) * 132 + rr];
                v.y = eb[(c4 + 1) * 132 + rr];
                v.z = eb[(c4 + 2) * 132 + rr];
                v.w = eb[(c4 + 3) * 132 + rr];
                *(float4*)&Cm[(long)rr * ldC + c4] = v;
            }
        }
    }
}

// --------------------------------- launch --------------------------------------
extern "C" void kernel_launch(void* const* d_in, const int* in_sizes, int n_in,
                              void* d_out, int out_size) {
    const float* key_soft = (const float*)d_in[0];   // [16,1024,256]
    const float* keys     = (const float*)d_in[1];   // [512,256]
    const float* vparams  = (const float*)d_in[2];   // [512,256]
    float* out = (float*)d_out;

    float* o_idx  = out;                             // [16384]
    float* o_vw   = o_idx  + MR;                     // [16384,256]
    float* o_hard = o_vw   + (long)MR * DD;          // [16384,256]
    float* o_vpss = o_hard + (long)MR * DD;          // [16,1024,1024]
    float* o_vpsh = o_vpss + (long)MR * TT;          // [16384,512]
    float* o_kss  = o_vpsh + (long)MR * NE;          // [16,1024,1024]
    float* o_ksh  = o_kss  + (long)MR * TT;          // [16384,512]

    __half *p_ksn_h, *p_wh, *p_keys_h, *p_vpn_h, *p_vpnT_h, *p_vwh;
    float *p_ksn_f, *p_keys_f, *p_vpn;
    cudaGetSymbolAddress((void**)&p_ksn_h,  g_ksn_h);
    cudaGetSymbolAddress((void**)&p_ksn_f,  g_ksn_f);
    cudaGetSymbolAddress((void**)&p_wh,     g_wh);
    cudaGetSymbolAddress((void**)&p_keys_h, g_keys_h);
    cudaGetSymbolAddress((void**)&p_keys_f, g_keys_f);
    cudaGetSymbolAddress((void**)&p_vpn,    g_vp_norm);
    cudaGetSymbolAddress((void**)&p_vpn_h,  g_vpn_h);
    cudaGetSymbolAddress((void**)&p_vpnT_h, g_vpnT_h);
    cudaGetSymbolAddress((void**)&p_vwh,    g_vwh);

    const int S1  = 3 * 4096 * 4;         // 49152: fp16 stages
    const int S1S = 128 * 132 * 4;        // 67584: sym epilogue (> stages)
    cudaFuncSetAttribute(gemm_h<false>,
                         cudaFuncAttributeMaxDynamicSharedMemorySize, S1);
    cudaFuncSetAttribute(gemm_h<true>,
                         cudaFuncAttributeMaxDynamicSharedMemorySize, S1S);

    // 1) normalize codebooks + inputs (fp32 + fp16 copies)
    rownorm_hl<<<NE / 8, 256>>>(keys,    p_keys_f, p_keys_h, NE);
    rownorm_hl<<<NE / 8, 256>>>(vparams, p_vpn,    p_vpn_h,  NE);
    transpose_vp<<<dim3(DD / 32, NE / 32), dim3(32, 32)>>>();
    rownorm_hl<<<MR / 8, 256>>>(key_soft, p_ksn_f, p_ksn_h, MR);

    // 2) score_ksh = ksn @ keys_norm^T  [16384,512]  (single-pass fp16)
    gemm_h<false><<<dim3(NE / 128, MR / 128, 1), 256, S1>>>(
        p_ksn_h, p_keys_h, o_ksh, DD, NE, 0, 0, 0);

    // 3) softmax + exact-argmax correction + hard gather
    softmax_argmax<<<MR, 256>>>(o_ksh, o_idx, o_hard);

    // 4) vw_raw = w @ vp_norm == w @ (vp_normT)^T  [16384,256]
    gemm_h<false><<<dim3(DD / 128, MR / 128, 1), 256, S1>>>(
        p_wh, p_vpnT_h, o_vw, NE, DD, 0, 0, 0);

    // 5) normalize vparams_w: fp32 in place + fp16 copy
    rownorm_hl<<<MR / 8, 256>>>(o_vw, o_vw, p_vwh, MR);

    // 6) score_vpsh = vparams_w @ vp_norm^T  [16384,512]
    gemm_h<false><<<dim3(NE / 128, MR / 128, 1), 256, S1>>>(
        p_vwh, p_vpn_h, o_vpsh, DD, NE, 0, 0, 0);

    // 7) score_kss = batched ksn_b @ ksn_b^T  [16,1024,1024]  (symmetric)
    gemm_h<true><<<dim3(36, 1, BB), 256, S1S>>>(
        p_ksn_h, p_ksn_h, o_kss, DD, TT,
        (long)TT * DD, (long)TT * DD, (long)TT * TT);

    // 8) score_vpss = batched vw_b @ vw_b^T  [16,1024,1024]  (symmetric)
    gemm_h<true><<<dim3(36, 1, BB), 256, S1S>>>(
        p_vwh, p_vwh, o_vpss, DD, TT,
        (long)TT * DD, (long)TT * DD, (long)TT * TT);
}

// round 9
// speedup vs baseline: 3.2969x; 1.0910x over previous
#include <cuda_runtime.h>
#include <cuda_fp16.h>
#include <math.h>
#include <stdint.h>

// Problem dims (fixed by the dataset)
#define BB   16
#define TT   1024
#define DD   256        // key_dim == e_dim
#define NE   512        // codebook size
#define MR   (BB*TT)    // 16384 rows

// ---------------- scratch (__device__ globals: allocation-free) ----------------
__device__ __half g_ksn_h[MR * DD];     // normalized key_soft, fp16
__device__ float  g_ksn_f[MR * DD];     // normalized key_soft, fp32 (argmax check)
__device__ __half g_wh[MR * NE];        // softmax weights fp16
__device__ __half g_keys_h[NE * DD];
__device__ float  g_keys_f[NE * DD];    // fp32 keys_norm (argmax check)
__device__ float  g_vp_norm[NE * DD];   // fp32 (exact gather source)
__device__ __half g_vpn_h[NE * DD];
__device__ __half g_vpnT_h[DD * NE];    // vp_norm transposed fp16 [E, n_e]
__device__ __half g_vwh[MR * DD];       // normalized vparams_w fp16

// =============================== aux kernels ===================================
// L2 normalize, 256 cols, 2 rows per warp (MLP=2); optional fp32 + fp16 outputs
__global__ void rownorm_hl(const float* __restrict__ in, float* __restrict__ of,
                           __half* __restrict__ oh, int nrows) {
    long w = (long)((blockIdx.x * blockDim.x + threadIdx.x) >> 5) * 2;
    int lane = threadIdx.x & 31;
    if (w >= nrows) return;
    const float4* ip0 = (const float4*)(in + w * 256);
    const float4* ip1 = (const float4*)(in + (w + 1) * 256);
    float4 a0 = ip0[lane], a1 = ip0[lane + 32];
    float4 b0 = ip1[lane], b1 = ip1[lane + 32];
    float s0 = a0.x*a0.x + a0.y*a0.y + a0.z*a0.z + a0.w*a0.w
             + a1.x*a1.x + a1.y*a1.y + a1.z*a1.z + a1.w*a1.w;
    float s1 = b0.x*b0.x + b0.y*b0.y + b0.z*b0.z + b0.w*b0.w
             + b1.x*b1.x + b1.y*b1.y + b1.z*b1.z + b1.w*b1.w;
    #pragma unroll
    for (int o = 16; o; o >>= 1) {
        s0 += __shfl_xor_sync(0xffffffffu, s0, o);
        s1 += __shfl_xor_sync(0xffffffffu, s1, o);
    }
    float k0 = 1.0f / fmaxf(sqrtf(s0), 1e-12f);
    float k1 = 1.0f / fmaxf(sqrtf(s1), 1e-12f);
    float4 r0 = make_float4(a0.x*k0, a0.y*k0, a0.z*k0, a0.w*k0);
    float4 r1 = make_float4(a1.x*k0, a1.y*k0, a1.z*k0, a1.w*k0);
    float4 r2 = make_float4(b0.x*k1, b0.y*k1, b0.z*k1, b0.w*k1);
    float4 r3 = make_float4(b1.x*k1, b1.y*k1, b1.z*k1, b1.w*k1);
    if (of) {
        float4* op0 = (float4*)(of + w * 256);
        float4* op1 = (float4*)(of + (w + 1) * 256);
        op0[lane] = r0; op0[lane + 32] = r1;
        op1[lane] = r2; op1[lane + 32] = r3;
    }
    __half2* hp0 = (__half2*)(oh + w * 256);
    __half2* hp1 = (__half2*)(oh + (w + 1) * 256);
    hp0[lane*2]        = __floats2half2_rn(r0.x, r0.y);
    hp0[lane*2+1]      = __floats2half2_rn(r0.z, r0.w);
    hp0[64 + lane*2]   = __floats2half2_rn(r1.x, r1.y);
    hp0[64 + lane*2+1] = __floats2half2_rn(r1.z, r1.w);
    hp1[lane*2]        = __floats2half2_rn(r2.x, r2.y);
    hp1[lane*2+1]      = __floats2half2_rn(r2.z, r2.w);
    hp1[64 + lane*2]   = __floats2half2_rn(r3.x, r3.y);
    hp1[64 + lane*2+1] = __floats2half2_rn(r3.z, r3.w);
}

__global__ void transpose_vp() {
    __shared__ float tile[32][33];
    int x = blockIdx.x * 32 + threadIdx.x;
    int y = blockIdx.y * 32 + threadIdx.y;
    tile[threadIdx.y][threadIdx.x] = g_vp_norm[y * 256 + x];
    __syncthreads();
    int tx = blockIdx.y * 32 + threadIdx.x;
    int ty = blockIdx.x * 32 + threadIdx.y;
    g_vpnT_h[ty * 512 + tx] = __float2half_rn(tile[threadIdx.x][threadIdx.y]);
}

// softmax + exact-argmax (fp32 candidate re-check) + hard gather, 1 block/row
__global__ void softmax_argmax(const float* __restrict__ ksh,
                               float* __restrict__ out_idx,
                               float* __restrict__ out_hard) {
    int r = blockIdx.x;
    int t = threadIdx.x;                  // 256 threads, 2 cols each
    const float* row = ksh + (long)r * NE;
    float s0 = row[t], s1 = row[t + 256];

    // 1) block max (value only)
    float bv = fmaxf(s0, s1);
    #pragma unroll
    for (int o = 16; o; o >>= 1) bv = fmaxf(bv, __shfl_xor_sync(0xffffffffu, bv, o));
    __shared__ float sv[8];
    if ((t & 31) == 0) sv[t >> 5] = bv;
    __syncthreads();
    if (t < 8) {
        float x = sv[t];
        #pragma unroll
        for (int o = 4; o; o >>= 1) x = fmaxf(x, __shfl_xor_sync(0xffu, x, o));
        if (t == 0) sv[0] = x;
    }
    __syncthreads();
    float m = sv[0];

    // 2) candidate collection (fp16 dot error bound ~1e-3; eps=3e-3 is 3x margin)
    __shared__ int   cnt;
    __shared__ short cand[512];
    __shared__ float4 xrow[64];
    if (t == 0) cnt = 0;
    ((float*)xrow)[t] = g_ksn_f[(long)r * 256 + t];
    __syncthreads();
    const float eps = 3e-3f;
    if (s0 >= m - eps) { int p = atomicAdd(&cnt, 1); cand[p] = (short)t; }
    if (s1 >= m - eps) { int p = atomicAdd(&cnt, 1); cand[p] = (short)(t + 256); }
    __syncthreads();

    // 3) warp 0: exact fp32 dots for candidates; pick max, tie -> lower index
    __shared__ int besti;
    if (t < 32) {
        float bv2 = -2e30f; int bi2 = 1 << 30;
        int n = cnt;
        for (int c = 0; c < n; c++) {
            int j = cand[c];
            const float4* kp = (const float4*)(g_keys_f + (long)j * 256);
            float4 u0 = kp[t*2], u1 = kp[t*2+1];
            float4 p0 = ((const float4*)xrow)[t*2];
            float4 p1 = ((const float4*)xrow)[t*2+1];
            float d = u0.x*p0.x + u0.y*p0.y + u0.z*p0.z + u0.w*p0.w
                    + u1.x*p1.x + u1.y*p1.y + u1.z*p1.z + u1.w*p1.w;
            #pragma unroll
            for (int o = 16; o; o >>= 1) d += __shfl_xor_sync(0xffffffffu, d, o);
            if (d > bv2 || (d == bv2 && j < bi2)) { bv2 = d; bi2 = j; }
        }
        if (t == 0) besti = bi2;
    }

    // 4) softmax over fp16-accurate scores (error ~1e-4: fine for w)
    float e0 = expf(s0 - m), e1 = expf(s1 - m);
    float s = e0 + e1;
    #pragma unroll
    for (int o = 16; o; o >>= 1) s += __shfl_xor_sync(0xffffffffu, s, o);
    __shared__ float ss[8];
    if ((t & 31) == 0) ss[t >> 5] = s;
    __syncthreads();
    if (t < 8) {
        float x = ss[t];
        #pragma unroll
        for (int o = 4; o; o >>= 1) x += __shfl_xor_sync(0xffu, x, o);
        if (t == 0) ss[0] = x;
    }
    __syncthreads();
    float inv = 1.0f / ss[0];
    g_wh[(long)r * NE + t]       = __float2half_rn(e0 * inv);
    g_wh[(long)r * NE + t + 256] = __float2half_rn(e1 * inv);
    int idx = besti;
    if (t == 0) out_idx[r] = (float)idx;
    out_hard[(long)r * 256 + t] = g_vp_norm[(long)idx * 256 + t];
}

// ==================== fp16 mma.sync GEMM (m16n8k16, sm_80+) ====================
// Unified kernel: blockIdx.x < nsCount  -> nonsym tile of C_ns = A_ns @ B_ns^T
//                 blockIdx.x >= nsCount -> symmetric Gram tile (batched, T=1024)
// Block tile 128x128, BK=32, 3-stage cp.async, 8 warps x (64x32), 2 CTAs/SM.
__device__ __forceinline__ void cp16(uint32_t saddr, const void* g) {
    asm volatile("cp.async.cg.shared.global [%0], [%1], 16;"
                 :: "r"(saddr), "l"(g) : "memory");
}
__device__ __forceinline__ void mma16(float* d, const uint32_t* a, const uint32_t* b) {
    asm volatile(
        "mma.sync.aligned.m16n8k16.row.col.f32.f16.f16.f32 "
        "{%0,%1,%2,%3}, {%4,%5,%6,%7}, {%8,%9}, {%0,%1,%2,%3};"
        : "+f"(d[0]), "+f"(d[1]), "+f"(d[2]), "+f"(d[3])
        : "r"(a[0]), "r"(a[1]), "r"(a[2]), "r"(a[3]), "r"(b[0]), "r"(b[1]));
}

__global__ __launch_bounds__(256, 2) void gemm_h(
    const __half* __restrict__ A_ns, const __half* __restrict__ B_ns,
    float* __restrict__ C_ns, int K, int ldC, int ntX, int nsCount,
    const __half* __restrict__ A_s, float* __restrict__ C_s)
{
    constexpr int BOFFU  = 2048;          // B u32 offset within stage
    constexpr int STAGEU = 4096;          // u32 per stage
    extern __shared__ uint32_t smu[];
    const int t = threadIdx.x;
    const int wid = t >> 5, lane = t & 31;
    const int g = lane >> 2, q = lane & 3;

    const int x = blockIdx.x;
    const bool sym = (x >= nsCount);
    int bi, bj;
    const __half *Ah, *Bh;
    long csOff = 0;
    if (!sym) {
        bi = x / ntX; bj = x % ntX;
        Ah = A_ns + (long)(bi * 128) * K;
        Bh = B_ns + (long)(bj * 128) * K;
    } else {
        int xs = x - nsCount;
        int bz = xs / 36, u = xs % 36, i = 0;
        while (u >= 8 - i) { u -= 8 - i; i++; }  // 36 pairs, i<=j
        bi = i; bj = i + u;
        const __half* base = A_s + (long)bz * TT * DD;   // K == DD here
        Ah = base + (long)(bi * 128) * K;
        Bh = base + (long)(bj * 128) * K;
        csOff = (long)bz * TT * TT;
    }

    // per-thread cp.async scatter targets (u32 units) + gmem offsets
    int aidx[2], bidx[2], goff[2];
    #pragma unroll
    for (int i = 0; i < 2; i++) {
        int fid = t + i * 256;            // 0..511
        int r = fid >> 2, c8 = fid & 3;   // row, 8-half quad
        int ks = c8 >> 1, hi = c8 & 1;
        goff[i] = r * K + c8 * 8;
        int mt = r >> 4, rl = r & 15;
        aidx[i] = (((ks * 8 + mt) * 4 + ((rl >> 3) + 2 * hi)) * 32)
                + (((rl & 7) ^ (ks * 2 + hi)) << 2);
        int nt = r >> 3, nl = r & 7;
        bidx[i] = BOFFU + (((ks * 16 + nt) * 2 + hi) * 32)
                + ((nl ^ (ks * 2 + hi)) << 2);
    }
    uint32_t smb = (uint32_t)__cvta_generic_to_shared(smu);

    auto issue = [&](int kc, int st) {
        uint32_t sb = smb + (uint32_t)(st * STAGEU) * 4u;
        #pragma unroll
        for (int i = 0; i < 2; i++) {
            cp16(sb + aidx[i] * 4, Ah + goff[i] + kc * 32);
            cp16(sb + bidx[i] * 4, Bh + goff[i] + kc * 32);
        }
        asm volatile("cp.async.commit_group;" ::: "memory");
    };

    float acc[4][4][4];
    #pragma unroll
    for (int mi = 0; mi < 4; mi++)
        #pragma unroll
        for (int ni = 0; ni < 4; ni++)
            #pragma unroll
            for (int j = 0; j < 4; j++) acc[mi][ni][j] = 0.0f;

    const int nk = K >> 5;                // >= 8 here
    issue(0, 0);
    issue(1, 1);

    for (int k = 0; k < nk; k++) {
        int st = k % 3;
        if (k + 1 < nk) asm volatile("cp.async.wait_group 1;" ::: "memory");
        else            asm volatile("cp.async.wait_group 0;" ::: "memory");
        __syncthreads();                   // single sync per iteration
        if (k + 2 < nk) issue(k + 2, (k + 2) % 3);

        const uint32_t* stg = smu + st * STAGEU;
        #pragma unroll
        for (int ks = 0; ks < 2; ks++) {
            uint32_t bhf[4][2];
            #pragma unroll
            for (int ni = 0; ni < 4; ni++) {
                int nt = (wid & 3) * 4 + ni;
                #pragma unroll
                for (int rg = 0; rg < 2; rg++) {
                    int off = BOFFU + ((ks * 16 + nt) * 2 + rg) * 32
                            + (((g ^ (ks * 2 + rg)) << 2) + q);
                    bhf[ni][rg] = stg[off];
                }
            }
            #pragma unroll
            for (int mi = 0; mi < 4; mi++) {
                int mt = (wid >> 2) * 4 + mi;
                uint32_t ahf[4];
                #pragma unroll
                for (int rg = 0; rg < 4; rg++) {
                    int off = ((ks * 8 + mt) * 4 + rg) * 32
                            + (((g ^ (ks * 2 + (rg >> 1))) << 2) + q);
                    ahf[rg] = stg[off];
                }
                #pragma unroll
                for (int ni = 0; ni < 4; ni++) mma16(acc[mi][ni], ahf, bhf[ni]);
            }
        }
    }

    if (!sym) {
        float* Cp = C_ns + (long)(bi * 128) * ldC + bj * 128;
        #pragma unroll
        for (int mi = 0; mi < 4; mi++) {
            int row = (wid >> 2) * 64 + mi * 16 + g;
            #pragma unroll
            for (int ni = 0; ni < 4; ni++) {
                int col = (wid & 3) * 32 + ni * 8 + q * 2;
                *(float2*)&Cp[(long)row * ldC + col] =
                    make_float2(acc[mi][ni][0], acc[mi][ni][1]);
                *(float2*)&Cp[(long)(row + 8) * ldC + col] =
                    make_float2(acc[mi][ni][2], acc[mi][ni][3]);
            }
        }
    } else {
        __syncthreads();                  // stages done; reuse smem
        float* eb = (float*)smu;          // 128 x 132 staging tile
        #pragma unroll
        for (int mi = 0; mi < 4; mi++) {
            int row = (wid >> 2) * 64 + mi * 16 + g;
            #pragma unroll
            for (int ni = 0; ni < 4; ni++) {
                int col = (wid & 3) * 32 + ni * 8 + q * 2;
                *(float2*)&eb[row * 132 + col] =
                    make_float2(acc[mi][ni][0], acc[mi][ni][1]);
                *(float2*)&eb[(row + 8) * 132 + col] =
                    make_float2(acc[mi][ni][2], acc[mi][ni][3]);
            }
        }
        __syncthreads();
        float* Cn = C_s + csOff + (long)(bi * 128) * TT + bj * 128;
        #pragma unroll
        for (int i2 = 0; i2 < 16; i2++) {
            int id = t + i2 * 256;
            int r = id >> 5, c4 = (id & 31) * 4;
            *(float4*)&Cn[(long)r * TT + c4] = *(float4*)&eb[r * 132 + c4];
        }
        if (bi != bj) {
            float* Cm = C_s + csOff + (long)(bj * 128) * TT + bi * 128;
            #pragma unroll
            for (int i2 = 0; i2 < 16; i2++) {
                int id = t + i2 * 256;
                int rr = id & 127, c4 = (id >> 7) * 4;   // conflict-free map
                float4 v;
                v.x = eb[(c4 + 0) * 132 + rr];
                v.y = eb[(c4 + 1) * 132 + rr];
                v.z = eb[(c4 + 2) * 132 + rr];
                v.w = eb[(c4 + 3) * 132 + rr];
                *(float4*)&Cm[(long)rr * TT + c4] = v;
            }
        }
    }
}

// --------------------------------- launch --------------------------------------
extern "C" void kernel_launch(void* const* d_in, const int* in_sizes, int n_in,
                              void* d_out, int out_size) {
    const float* key_soft = (const float*)d_in[0];   // [16,1024,256]
    const float* keys     = (const float*)d_in[1];   // [512,256]
    const float* vparams  = (const float*)d_in[2];   // [512,256]
    float* out = (float*)d_out;

    float* o_idx  = out;                             // [16384]
    float* o_vw   = o_idx  + MR;                     // [16384,256]
    float* o_hard = o_vw   + (long)MR * DD;          // [16384,256]
    float* o_vpss = o_hard + (long)MR * DD;          // [16,1024,1024]
    float* o_vpsh = o_vpss + (long)MR * TT;          // [16384,512]
    float* o_kss  = o_vpsh + (long)MR * NE;          // [16,1024,1024]
    float* o_ksh  = o_kss  + (long)MR * TT;          // [16384,512]

    __half *p_ksn_h, *p_wh, *p_keys_h, *p_vpn_h, *p_vpnT_h, *p_vwh;
    float *p_ksn_f, *p_keys_f, *p_vpn;
    cudaGetSymbolAddress((void**)&p_ksn_h,  g_ksn_h);
    cudaGetSymbolAddress((void**)&p_ksn_f,  g_ksn_f);
    cudaGetSymbolAddress((void**)&p_wh,     g_wh);
    cudaGetSymbolAddress((void**)&p_keys_h, g_keys_h);
    cudaGetSymbolAddress((void**)&p_keys_f, g_keys_f);
    cudaGetSymbolAddress((void**)&p_vpn,    g_vp_norm);
    cudaGetSymbolAddress((void**)&p_vpn_h,  g_vpn_h);
    cudaGetSymbolAddress((void**)&p_vpnT_h, g_vpnT_h);
    cudaGetSymbolAddress((void**)&p_vwh,    g_vwh);

    const int SMX = 128 * 132 * 4;        // 67584: sym epilogue (>= stage bytes)
    const int S1  = 3 * 4096 * 4;         // 49152: stages only (nonsym-only call)
    cudaFuncSetAttribute(gemm_h, cudaFuncAttributeMaxDynamicSharedMemorySize, SMX);

    // 1) normalize codebooks + inputs (fp32 + fp16 copies)
    rownorm_hl<<<NE / 16, 256>>>(keys,    p_keys_f, p_keys_h, NE);
    rownorm_hl<<<NE / 16, 256>>>(vparams, p_vpn,    p_vpn_h,  NE);
    transpose_vp<<<dim3(DD / 32, NE / 32), dim3(32, 32)>>>();
    rownorm_hl<<<MR / 16, 256>>>(key_soft, p_ksn_f, p_ksn_h, MR);

    // 2) FUSED: score_ksh (512 nonsym tiles) + score_kss (576 sym tiles)
    gemm_h<<<512 + 36 * BB, 256, SMX>>>(
        p_ksn_h, p_keys_h, o_ksh, DD, NE, NE / 128, 512,
        p_ksn_h, o_kss);

    // 3) softmax + exact-argmax correction + hard gather
    softmax_argmax<<<MR, 256>>>(o_ksh, o_idx, o_hard);

    // 4) vw_raw = w @ vp_norm == w @ (vp_normT)^T  [16384,256]
    gemm_h<<<(DD / 128) * (MR / 128), 256, S1>>>(
        p_wh, p_vpnT_h, o_vw, NE, DD, DD / 128, (DD / 128) * (MR / 128),
        nullptr, nullptr);

    // 5) normalize vparams_w: fp32 in place + fp16 copy
    rownorm_hl<<<MR / 16, 256>>>(o_vw, o_vw, p_vwh, MR);

    // 6) FUSED: score_vpsh (512 nonsym tiles) + score_vpss (576 sym tiles)
    gemm_h<<<512 + 36 * BB, 256, SMX>>>(
        p_vwh, p_vpn_h, o_vpsh, DD, NE, NE / 128, 512,
        p_vwh, o_vpss);
}

// round 10
// speedup vs baseline: 4.4329x; 1.3446x over previous
#include <cuda_runtime.h>
#include <cuda_fp16.h>
#include <math.h>
#include <stdint.h>

// Problem dims (fixed by the dataset)
#define BB   16
#define TT   1024
#define DD   256        // key_dim == e_dim
#define NE   512        // codebook size
#define MR   (BB*TT)    // 16384 rows

// ---------------- scratch (__device__ globals: allocation-free) ----------------
__device__ __half g_ksn_h[MR * DD];     // normalized key_soft, fp16
__device__ float  g_ksn_f[MR * DD];     // normalized key_soft, fp32 (argmax check)
__device__ __half g_wh[MR * NE];        // softmax weights fp16
__device__ __half g_keys_h[NE * DD];
__device__ float  g_keys_f[NE * DD];    // fp32 keys_norm (argmax check)
__device__ float  g_vp_norm[NE * DD];   // fp32 (exact gather source)
__device__ __half g_vpn_h[NE * DD];
__device__ __half g_vpnT_h[DD * NE];    // vp_norm transposed fp16 [E, n_e]
__device__ __half g_vwh[MR * DD];       // normalized vparams_w fp16

// =============================== aux kernels ===================================
// L2 normalize, 256 cols, 2 rows per warp (MLP=2); optional fp32 + fp16 outputs
__global__ void rownorm_hl(const float* __restrict__ in, float* __restrict__ of,
                           __half* __restrict__ oh, int nrows) {
    long w = (long)((blockIdx.x * blockDim.x + threadIdx.x) >> 5) * 2;
    int lane = threadIdx.x & 31;
    if (w >= nrows) return;
    const float4* ip0 = (const float4*)(in + w * 256);
    const float4* ip1 = (const float4*)(in + (w + 1) * 256);
    float4 a0 = ip0[lane], a1 = ip0[lane + 32];
    float4 b0 = ip1[lane], b1 = ip1[lane + 32];
    float s0 = a0.x*a0.x + a0.y*a0.y + a0.z*a0.z + a0.w*a0.w
             + a1.x*a1.x + a1.y*a1.y + a1.z*a1.z + a1.w*a1.w;
    float s1 = b0.x*b0.x + b0.y*b0.y + b0.z*b0.z + b0.w*b0.w
             + b1.x*b1.x + b1.y*b1.y + b1.z*b1.z + b1.w*b1.w;
    #pragma unroll
    for (int o = 16; o; o >>= 1) {
        s0 += __shfl_xor_sync(0xffffffffu, s0, o);
        s1 += __shfl_xor_sync(0xffffffffu, s1, o);
    }
    float k0 = 1.0f / fmaxf(sqrtf(s0), 1e-12f);
    float k1 = 1.0f / fmaxf(sqrtf(s1), 1e-12f);
    float4 r0 = make_float4(a0.x*k0, a0.y*k0, a0.z*k0, a0.w*k0);
    float4 r1 = make_float4(a1.x*k0, a1.y*k0, a1.z*k0, a1.w*k0);
    float4 r2 = make_float4(b0.x*k1, b0.y*k1, b0.z*k1, b0.w*k1);
    float4 r3 = make_float4(b1.x*k1, b1.y*k1, b1.z*k1, b1.w*k1);
    if (of) {
        float4* op0 = (float4*)(of + w * 256);
        float4* op1 = (float4*)(of + (w + 1) * 256);
        op0[lane] = r0; op0[lane + 32] = r1;
        op1[lane] = r2; op1[lane + 32] = r3;
    }
    __half2* hp0 = (__half2*)(oh + w * 256);
    __half2* hp1 = (__half2*)(oh + (w + 1) * 256);
    hp0[lane*2]        = __floats2half2_rn(r0.x, r0.y);
    hp0[lane*2+1]      = __floats2half2_rn(r0.z, r0.w);
    hp0[64 + lane*2]   = __floats2half2_rn(r1.x, r1.y);
    hp0[64 + lane*2+1] = __floats2half2_rn(r1.z, r1.w);
    hp1[lane*2]        = __floats2half2_rn(r2.x, r2.y);
    hp1[lane*2+1]      = __floats2half2_rn(r2.z, r2.w);
    hp1[64 + lane*2]   = __floats2half2_rn(r3.x, r3.y);
    hp1[64 + lane*2+1] = __floats2half2_rn(r3.z, r3.w);
}

__global__ void transpose_vp() {
    __shared__ float tile[32][33];
    int x = blockIdx.x * 32 + threadIdx.x;
    int y = blockIdx.y * 32 + threadIdx.y;
    tile[threadIdx.y][threadIdx.x] = g_vp_norm[y * 256 + x];
    __syncthreads();
    int tx = blockIdx.y * 32 + threadIdx.x;
    int ty = blockIdx.x * 32 + threadIdx.y;
    g_vpnT_h[ty * 512 + tx] = __float2half_rn(tile[threadIdx.x][threadIdx.y]);
}

// softmax + exact-argmax (fp32 candidate re-check) + hard gather, 1 block/row
__global__ void softmax_argmax(const float* __restrict__ ksh,
                               float* __restrict__ out_idx,
                               float* __restrict__ out_hard) {
    int r = blockIdx.x;
    int t = threadIdx.x;                  // 256 threads, 2 cols each
    const float* row = ksh + (long)r * NE;
    float s0 = row[t], s1 = row[t + 256];

    // 1) block max (value only)
    float bv = fmaxf(s0, s1);
    #pragma unroll
    for (int o = 16; o; o >>= 1) bv = fmaxf(bv, __shfl_xor_sync(0xffffffffu, bv, o));
    __shared__ float sv[8];
    if ((t & 31) == 0) sv[t >> 5] = bv;
    __syncthreads();
    if (t < 8) {
        float x = sv[t];
        #pragma unroll
        for (int o = 4; o; o >>= 1) x = fmaxf(x, __shfl_xor_sync(0xffu, x, o));
        if (t == 0) sv[0] = x;
    }
    __syncthreads();
    float m = sv[0];

    // 2) candidate collection (fp16 dot error bound ~1e-3; eps=3e-3 is 3x margin)
    __shared__ int   cnt;
    __shared__ short cand[512];
    __shared__ float4 xrow[64];
    if (t == 0) cnt = 0;
    ((float*)xrow)[t] = g_ksn_f[(long)r * 256 + t];
    __syncthreads();
    const float eps = 3e-3f;
    if (s0 >= m - eps) { int p = atomicAdd(&cnt, 1); cand[p] = (short)t; }
    if (s1 >= m - eps) { int p = atomicAdd(&cnt, 1); cand[p] = (short)(t + 256); }
    __syncthreads();

    // 3) warp 0: exact fp32 dots for candidates; pick max, tie -> lower index
    __shared__ int besti;
    if (t < 32) {
        float bv2 = -2e30f; int bi2 = 1 << 30;
        int n = cnt;
        for (int c = 0; c < n; c++) {
            int j = cand[c];
            const float4* kp = (const float4*)(g_keys_f + (long)j * 256);
            float4 u0 = kp[t*2], u1 = kp[t*2+1];
            float4 p0 = ((const float4*)xrow)[t*2];
            float4 p1 = ((const float4*)xrow)[t*2+1];
            float d = u0.x*p0.x + u0.y*p0.y + u0.z*p0.z + u0.w*p0.w
                    + u1.x*p1.x + u1.y*p1.y + u1.z*p1.z + u1.w*p1.w;
            #pragma unroll
            for (int o = 16; o; o >>= 1) d += __shfl_xor_sync(0xffffffffu, d, o);
            if (d > bv2 || (d == bv2 && j < bi2)) { bv2 = d; bi2 = j; }
        }
        if (t == 0) besti = bi2;
    }

    // 4) softmax over fp16-accurate scores (error ~1e-4: fine for w)
    float e0 = expf(s0 - m), e1 = expf(s1 - m);
    float s = e0 + e1;
    #pragma unroll
    for (int o = 16; o; o >>= 1) s += __shfl_xor_sync(0xffffffffu, s, o);
    __shared__ float ss[8];
    if ((t & 31) == 0) ss[t >> 5] = s;
    __syncthreads();
    if (t < 8) {
        float x = ss[t];
        #pragma unroll
        for (int o = 4; o; o >>= 1) x += __shfl_xor_sync(0xffu, x, o);
        if (t == 0) ss[0] = x;
    }
    __syncthreads();
    float inv = 1.0f / ss[0];
    g_wh[(long)r * NE + t]       = __float2half_rn(e0 * inv);
    g_wh[(long)r * NE + t + 256] = __float2half_rn(e1 * inv);
    int idx = besti;
    if (t == 0) out_idx[r] = (float)idx;
    out_hard[(long)r * 256 + t] = g_vp_norm[(long)idx * 256 + t];
}

// ============= fp16 mma.sync GEMM with ldmatrix (m16n8k16, sm_80+) =============
// Unified kernel: blockIdx.x < nsCount  -> nonsym tile of C_ns = A_ns @ B_ns^T
//                 blockIdx.x >= nsCount -> symmetric Gram tile (batched, T=1024)
// Block tile 128x128, BK=32, 3-stage cp.async, 8 warps x (64x32), 2 CTAs/SM.
// SMEM per stage: A[128 rows][32 halves] + B[...] as 64B rows of 4x16B chunks,
// chunk swizzle c^((r>>1)&3): conflict-free for 16B writes AND ldmatrix phases.
__device__ __forceinline__ void cp16(uint32_t saddr, const void* g) {
    asm volatile("cp.async.cg.shared.global [%0], [%1], 16;"
                 :: "r"(saddr), "l"(g) : "memory");
}
__device__ __forceinline__ void ldsm4(uint32_t* r, uint32_t addr) {
    asm volatile("ldmatrix.sync.aligned.m8n8.x4.shared.b16 {%0,%1,%2,%3}, [%4];"
                 : "=r"(r[0]), "=r"(r[1]), "=r"(r[2]), "=r"(r[3]) : "r"(addr));
}
__device__ __forceinline__ void mma16(float* d, const uint32_t* a, const uint32_t* b) {
    asm volatile(
        "mma.sync.aligned.m16n8k16.row.col.f32.f16.f16.f32 "
        "{%0,%1,%2,%3}, {%4,%5,%6,%7}, {%8,%9}, {%0,%1,%2,%3};"
        : "+f"(d[0]), "+f"(d[1]), "+f"(d[2]), "+f"(d[3])
        : "r"(a[0]), "r"(a[1]), "r"(a[2]), "r"(a[3]), "r"(b[0]), "r"(b[1]));
}

#define STAGE_B 16384   // bytes per stage (A 8192 + B 8192)

__global__ __launch_bounds__(256, 2) void gemm_h(
    const __half* __restrict__ A_ns, const __half* __restrict__ B_ns,
    float* __restrict__ C_ns, int K, int ldC, int ntX, int nsCount,
    const __half* __restrict__ A_s, float* __restrict__ C_s)
{
    extern __shared__ uint32_t smu[];
    const int t = threadIdx.x;
    const int wid = t >> 5, lane = t & 31;
    const int g = lane >> 2, q = lane & 3;

    const int x = blockIdx.x;
    const bool sym = (x >= nsCount);
    int bi, bj;
    const __half *Ah, *Bh;
    long csOff = 0;
    if (!sym) {
        bi = x / ntX; bj = x % ntX;
        Ah = A_ns + (long)(bi * 128) * K;
        Bh = B_ns + (long)(bj * 128) * K;
    } else {
        int xs = x - nsCount;
        int bz = xs / 36, u = xs % 36, i = 0;
        while (u >= 8 - i) { u -= 8 - i; i++; }  // 36 pairs, i<=j
        bi = i; bj = i + u;
        const __half* base = A_s + (long)bz * TT * DD;   // K == DD here
        Ah = base + (long)(bi * 128) * K;
        Bh = base + (long)(bj * 128) * K;
        csOff = (long)bz * TT * TT;
    }

    uint32_t smb = (uint32_t)__cvta_generic_to_shared(smu);

    // ---- writer precompute: 4 x 16B cp.async per thread (2 A rows, 2 B rows)
    const int wr = t >> 2, wc = t & 3;                   // row 0..63, chunk 0..3
    const uint32_t wdst = (uint32_t)(wr * 64 + ((wc ^ ((wr >> 1) & 3)) << 4));
    const long  gsrc = (long)wr * K + wc * 8;            // halves
    const long  gstep = (long)64 * K;

    auto issue = [&](int kc, int st) {
        uint32_t sb = smb + (uint32_t)st * STAGE_B;
        const __half* ap = Ah + gsrc + kc * 32;
        const __half* bp = Bh + gsrc + kc * 32;
        cp16(sb + wdst,        ap);
        cp16(sb + wdst + 4096, ap + gstep);
        cp16(sb + 8192 + wdst,        bp);
        cp16(sb + 8192 + wdst + 4096, bp + gstep);
        asm volatile("cp.async.commit_group;" ::: "memory");
    };

    // ---- reader precompute: ldmatrix lane addresses (all lane-constant bases)
    const int mbase = (wid >> 2) * 64, nbase = (wid & 3) * 32;
    const int rA  = (lane & 7) + ((lane >> 3) & 1) * 8;  // row within 16-row tile
    const int cA  = lane >> 4;                           // k-chunk bit
    const int swA = (rA >> 1) & 3;
    const uint32_t laneA = (uint32_t)((mbase + rA) * 64);
    const int rB  = ((lane >> 4) << 3) + (lane & 7);
    const int cB  = (lane >> 3) & 1;
    const int swB = (rB >> 1) & 3;
    const uint32_t laneB = (uint32_t)(8192 + (nbase + rB) * 64);

    float acc[4][4][4];
    #pragma unroll
    for (int mi = 0; mi < 4; mi++)
        #pragma unroll
        for (int ni = 0; ni < 4; ni++)
            #pragma unroll
            for (int j = 0; j < 4; j++) acc[mi][ni][j] = 0.0f;

    const int nk = K >> 5;                // >= 8 here
    issue(0, 0);
    issue(1, 1);

    for (int k = 0; k < nk; k++) {
        int st = k % 3;
        if (k + 1 < nk) asm volatile("cp.async.wait_group 1;" ::: "memory");
        else            asm volatile("cp.async.wait_group 0;" ::: "memory");
        __syncthreads();                   // single sync per iteration
        if (k + 2 < nk) issue(k + 2, (k + 2) % 3);

        uint32_t sb = smb + (uint32_t)st * STAGE_B;
        #pragma unroll
        for (int ks = 0; ks < 2; ks++) {
            uint32_t koffA = (uint32_t)(((ks * 2 + cA) ^ swA) << 4);
            uint32_t koffB = (uint32_t)(((ks * 2 + cB) ^ swB) << 4);
            uint32_t bF[4][2];
            {
                uint32_t tmp[4];
                ldsm4(tmp, sb + laneB + koffB);          // nt 0,1
                bF[0][0] = tmp[0]; bF[0][1] = tmp[1];
                bF[1][0] = tmp[2]; bF[1][1] = tmp[3];
                ldsm4(tmp, sb + laneB + 1024 + koffB);   // nt 2,3
                bF[2][0] = tmp[0]; bF[2][1] = tmp[1];
                bF[3][0] = tmp[2]; bF[3][1] = tmp[3];
            }
            #pragma unroll
            for (int mi = 0; mi < 4; mi++) {
                uint32_t aF[4];
                ldsm4(aF, sb + laneA + (uint32_t)(mi * 1024) + koffA);
                #pragma unroll
                for (int ni = 0; ni < 4; ni++) mma16(acc[mi][ni], aF, bF[ni]);
            }
        }
    }

    if (!sym) {
        float* Cp = C_ns + (long)(bi * 128) * ldC + bj * 128;
        #pragma unroll
        for (int mi = 0; mi < 4; mi++) {
            int row = (wid >> 2) * 64 + mi * 16 + g;
            #pragma unroll
            for (int ni = 0; ni < 4; ni++) {
                int col = (wid & 3) * 32 + ni * 8 + q * 2;
                *(float2*)&Cp[(long)row * ldC + col] =
                    make_float2(acc[mi][ni][0], acc[mi][ni][1]);
                *(float2*)&Cp[(long)(row + 8) * ldC + col] =
                    make_float2(acc[mi][ni][2], acc[mi][ni][3]);
            }
        }
    } else {
        __syncthreads();                  // stages done; reuse smem
        float* eb = (float*)smu;          // 128 x 132 staging tile
        #pragma unroll
        for (int mi = 0; mi < 4; mi++) {
            int row = (wid >> 2) * 64 + mi * 16 + g;
            #pragma unroll
            for (int ni = 0; ni < 4; ni++) {
                int col = (wid & 3) * 32 + ni * 8 + q * 2;
                *(float2*)&eb[row * 132 + col] =
                    make_float2(acc[mi][ni][0], acc[mi][ni][1]);
                *(float2*)&eb[(row + 8) * 132 + col] =
                    make_float2(acc[mi][ni][2], acc[mi][ni][3]);
            }
        }
        __syncthreads();
        float* Cn = C_s + csOff + (long)(bi * 128) * TT + bj * 128;
        #pragma unroll
        for (int i2 = 0; i2 < 16; i2++) {
            int id = t + i2 * 256;
            int r = id >> 5, c4 = (id & 31) * 4;
            *(float4*)&Cn[(long)r * TT + c4] = *(float4*)&eb[r * 132 + c4];
        }
        if (bi != bj) {
            float* Cm = C_s + csOff + (long)(bj * 128) * TT + bi * 128;
            #pragma unroll
            for (int i2 = 0; i2 < 16; i2++) {
                int id = t + i2 * 256;
                int rr = id & 127, c4 = (id >> 7) * 4;   // conflict-free map
                float4 v;
                v.x = eb[(c4 + 0) * 132 + rr];
                v.y = eb[(c4 + 1) * 132 + rr];
                v.z = eb[(c4 + 2) * 132 + rr];
                v.w = eb[(c4 + 3) * 132 + rr];
                *(float4*)&Cm[(long)rr * TT + c4] = v;
            }
        }
    }
}

// --------------------------------- launch --------------------------------------
extern "C" void kernel_launch(void* const* d_in, const int* in_sizes, int n_in,
                              void* d_out, int out_size) {
    const float* key_soft = (const float*)d_in[0];   // [16,1024,256]
    const float* keys     = (const float*)d_in[1];   // [512,256]
    const float* vparams  = (const float*)d_in[2];   // [512,256]
    float* out = (float*)d_out;

    float* o_idx  = out;                             // [16384]
    float* o_vw   = o_idx  + MR;                     // [16384,256]
    float* o_hard = o_vw   + (long)MR * DD;          // [16384,256]
    float* o_vpss = o_hard + (long)MR * DD;          // [16,1024,1024]
    float* o_vpsh = o_vpss + (long)MR * TT;          // [16384,512]
    float* o_kss  = o_vpsh + (long)MR * NE;          // [16,1024,1024]
    float* o_ksh  = o_kss  + (long)MR * TT;          // [16384,512]

    __half *p_ksn_h, *p_wh, *p_keys_h, *p_vpn_h, *p_vpnT_h, *p_vwh;
    float *p_ksn_f, *p_keys_f, *p_vpn;
    cudaGetSymbolAddress((void**)&p_ksn_h,  g_ksn_h);
    cudaGetSymbolAddress((void**)&p_ksn_f,  g_ksn_f);
    cudaGetSymbolAddress((void**)&p_wh,     g_wh);
    cudaGetSymbolAddress((void**)&p_keys_h, g_keys_h);
    cudaGetSymbolAddress((void**)&p_keys_f, g_keys_f);
    cudaGetSymbolAddress((void**)&p_vpn,    g_vp_norm);
    cudaGetSymbolAddress((void**)&p_vpn_h,  g_vpn_h);
    cudaGetSymbolAddress((void**)&p_vpnT_h, g_vpnT_h);
    cudaGetSymbolAddress((void**)&p_vwh,    g_vwh);

    const int SMX = 128 * 132 * 4;        // 67584: sym epilogue (>= stage bytes)
    const int S1  = 3 * STAGE_B;          // 49152: stages only (nonsym-only call)
    cudaFuncSetAttribute(gemm_h, cudaFuncAttributeMaxDynamicSharedMemorySize, SMX);

    // 1) normalize codebooks + inputs (fp32 + fp16 copies)
    rownorm_hl<<<NE / 16, 256>>>(keys,    p_keys_f, p_keys_h, NE);
    rownorm_hl<<<NE / 16, 256>>>(vparams, p_vpn,    p_vpn_h,  NE);
    transpose_vp<<<dim3(DD / 32, NE / 32), dim3(32, 32)>>>();
    rownorm_hl<<<MR / 16, 256>>>(key_soft, p_ksn_f, p_ksn_h, MR);

    // 2) FUSED: score_ksh (512 nonsym tiles) + score_kss (576 sym tiles)
    gemm_h<<<512 + 36 * BB, 256, SMX>>>(
        p_ksn_h, p_keys_h, o_ksh, DD, NE, NE / 128, 512,
        p_ksn_h, o_kss);

    // 3) softmax + exact-argmax correction + hard gather
    softmax_argmax<<<MR, 256>>>(o_ksh, o_idx, o_hard);

    // 4) vw_raw = w @ vp_norm == w @ (vp_normT)^T  [16384,256]
    gemm_h<<<(DD / 128) * (MR / 128), 256, S1>>>(
        p_wh, p_vpnT_h, o_vw, NE, DD, DD / 128, (DD / 128) * (MR / 128),
        nullptr, nullptr);

    // 5) normalize vparams_w: fp32 in place + fp16 copy
    rownorm_hl<<<MR / 16, 256>>>(o_vw, o_vw, p_vwh, MR);

    // 6) FUSED: score_vpsh (512 nonsym tiles) + score_vpss (576 sym tiles)
    gemm_h<<<512 + 36 * BB, 256, SMX>>>(
        p_vwh, p_vpn_h, o_vpsh, DD, NE, NE / 128, 512,
        p_vwh, o_vpss);
}

// round 11
// speedup vs baseline: 4.9046x; 1.1064x over previous
#include <cuda_runtime.h>
#include <cuda_fp16.h>
#include <math.h>
#include <stdint.h>

// Problem dims (fixed by the dataset)
#define BB   16
#define TT   1024
#define DD   256        // key_dim == e_dim
#define NE   512        // codebook size
#define MR   (BB*TT)    // 16384 rows

// ---------------- scratch (__device__ globals: allocation-free) ----------------
__device__ __half g_ksn_h[MR * DD];     // normalized key_soft, fp16
__device__ float  g_ksn_f[MR * DD];     // normalized key_soft, fp32 (argmax check)
__device__ __half g_wh[MR * NE];        // softmax weights fp16
__device__ __half g_keys_h[NE * DD];
__device__ float  g_keys_f[NE * DD];    // fp32 keys_norm (argmax check)
__device__ float  g_vp_norm[NE * DD];   // fp32 (exact gather source)
__device__ __half g_vpn_h[NE * DD];
__device__ __half g_vpnT_h[DD * NE];    // vp_norm transposed fp16 [E, n_e]
__device__ __half g_vwh[MR * DD];       // normalized vparams_w fp16

// =============================== aux kernels ===================================
// L2 normalize, 256 cols, 2 rows per warp (MLP=2); optional fp32 + fp16 outputs
__global__ void rownorm_hl(const float* __restrict__ in, float* __restrict__ of,
                           __half* __restrict__ oh, int nrows) {
    long w = (long)((blockIdx.x * blockDim.x + threadIdx.x) >> 5) * 2;
    int lane = threadIdx.x & 31;
    if (w >= nrows) return;
    const float4* ip0 = (const float4*)(in + w * 256);
    const float4* ip1 = (const float4*)(in + (w + 1) * 256);
    float4 a0 = ip0[lane], a1 = ip0[lane + 32];
    float4 b0 = ip1[lane], b1 = ip1[lane + 32];
    float s0 = a0.x*a0.x + a0.y*a0.y + a0.z*a0.z + a0.w*a0.w
             + a1.x*a1.x + a1.y*a1.y + a1.z*a1.z + a1.w*a1.w;
    float s1 = b0.x*b0.x + b0.y*b0.y + b0.z*b0.z + b0.w*b0.w
             + b1.x*b1.x + b1.y*b1.y + b1.z*b1.z + b1.w*b1.w;
    #pragma unroll
    for (int o = 16; o; o >>= 1) {
        s0 += __shfl_xor_sync(0xffffffffu, s0, o);
        s1 += __shfl_xor_sync(0xffffffffu, s1, o);
    }
    float k0 = 1.0f / fmaxf(sqrtf(s0), 1e-12f);
    float k1 = 1.0f / fmaxf(sqrtf(s1), 1e-12f);
    float4 r0 = make_float4(a0.x*k0, a0.y*k0, a0.z*k0, a0.w*k0);
    float4 r1 = make_float4(a1.x*k0, a1.y*k0, a1.z*k0, a1.w*k0);
    float4 r2 = make_float4(b0.x*k1, b0.y*k1, b0.z*k1, b0.w*k1);
    float4 r3 = make_float4(b1.x*k1, b1.y*k1, b1.z*k1, b1.w*k1);
    if (of) {
        float4* op0 = (float4*)(of + w * 256);
        float4* op1 = (float4*)(of + (w + 1) * 256);
        op0[lane] = r0; op0[lane + 32] = r1;
        op1[lane] = r2; op1[lane + 32] = r3;
    }
    __half2* hp0 = (__half2*)(oh + w * 256);
    __half2* hp1 = (__half2*)(oh + (w + 1) * 256);
    hp0[lane*2]        = __floats2half2_rn(r0.x, r0.y);
    hp0[lane*2+1]      = __floats2half2_rn(r0.z, r0.w);
    hp0[64 + lane*2]   = __floats2half2_rn(r1.x, r1.y);
    hp0[64 + lane*2+1] = __floats2half2_rn(r1.z, r1.w);
    hp1[lane*2]        = __floats2half2_rn(r2.x, r2.y);
    hp1[lane*2+1]      = __floats2half2_rn(r2.z, r2.w);
    hp1[64 + lane*2]   = __floats2half2_rn(r3.x, r3.y);
    hp1[64 + lane*2+1] = __floats2half2_rn(r3.z, r3.w);
}

__global__ void transpose_vp() {
    __shared__ float tile[32][33];
    int x = blockIdx.x * 32 + threadIdx.x;
    int y = blockIdx.y * 32 + threadIdx.y;
    tile[threadIdx.y][threadIdx.x] = g_vp_norm[y * 256 + x];
    __syncthreads();
    int tx = blockIdx.y * 32 + threadIdx.x;
    int ty = blockIdx.x * 32 + threadIdx.y;
    g_vpnT_h[ty * 512 + tx] = __float2half_rn(tile[threadIdx.x][threadIdx.y]);
}

// warp-per-row softmax + exact-argmax (fp32 candidate re-check) + hard gather
__global__ void softmax_argmax(const float* __restrict__ ksh,
                               float* __restrict__ out_idx,
                               float* __restrict__ out_hard) {
    int r = (blockIdx.x * blockDim.x + threadIdx.x) >> 5;
    int lane = threadIdx.x & 31;
    if (r >= MR) return;
    const float4* row4 = (const float4*)(ksh + (long)r * NE);
    float4 v[4];
    #pragma unroll
    for (int i = 0; i < 4; i++) v[i] = row4[i * 32 + lane];
    // warp max
    float m = -2e30f;
    #pragma unroll
    for (int i = 0; i < 4; i++)
        m = fmaxf(m, fmaxf(fmaxf(v[i].x, v[i].y), fmaxf(v[i].z, v[i].w)));
    #pragma unroll
    for (int o = 16; o; o >>= 1) m = fmaxf(m, __shfl_xor_sync(0xffffffffu, m, o));

    // fp32 query row (for exact re-check)
    const float4* xr4 = (const float4*)(g_ksn_f + (long)r * 256);
    float4 x0 = xr4[lane * 2], x1 = xr4[lane * 2 + 1];

    // candidate mask: fp16 dot error (input rounding + fp16-acc) << eps
    const float eps = 6e-3f;
    unsigned pend = 0;
    #pragma unroll
    for (int i = 0; i < 4; i++) {
        if (v[i].x >= m - eps) pend |= 1u << (i * 4 + 0);
        if (v[i].y >= m - eps) pend |= 1u << (i * 4 + 1);
        if (v[i].z >= m - eps) pend |= 1u << (i * 4 + 2);
        if (v[i].w >= m - eps) pend |= 1u << (i * 4 + 3);
    }
    float bv = -2e30f; int bi = 1 << 30;
    while (true) {
        unsigned act = __ballot_sync(0xffffffffu, pend != 0);
        if (!act) break;
        int leader = __ffs(act) - 1;
        int slot = (pend ? __ffs(pend) - 1 : 0);
        slot = __shfl_sync(0xffffffffu, slot, leader);
        int j = (slot >> 2) * 128 + leader * 4 + (slot & 3);
        const float4* kp = (const float4*)(g_keys_f + (long)j * 256);
        float4 u0 = kp[lane * 2], u1 = kp[lane * 2 + 1];
        float d = u0.x*x0.x + u0.y*x0.y + u0.z*x0.z + u0.w*x0.w
                + u1.x*x1.x + u1.y*x1.y + u1.z*x1.z + u1.w*x1.w;
        #pragma unroll
        for (int o = 16; o; o >>= 1) d += __shfl_xor_sync(0xffffffffu, d, o);
        if (d > bv || (d == bv && j < bi)) { bv = d; bi = j; }
        if (lane == leader) pend &= pend - 1;
    }

    // softmax (fp16-accurate scores: fine for w)
    float e[16];
    float sum = 0.0f;
    #pragma unroll
    for (int i = 0; i < 4; i++) {
        e[i*4+0] = expf(v[i].x - m); e[i*4+1] = expf(v[i].y - m);
        e[i*4+2] = expf(v[i].z - m); e[i*4+3] = expf(v[i].w - m);
        sum += e[i*4+0] + e[i*4+1] + e[i*4+2] + e[i*4+3];
    }
    #pragma unroll
    for (int o = 16; o; o >>= 1) sum += __shfl_xor_sync(0xffffffffu, sum, o);
    float inv = 1.0f / sum;
    __half2* wp = (__half2*)(g_wh + (long)r * NE);
    #pragma unroll
    for (int i = 0; i < 4; i++) {
        wp[i*64 + lane*2]     = __floats2half2_rn(e[i*4+0]*inv, e[i*4+1]*inv);
        wp[i*64 + lane*2 + 1] = __floats2half2_rn(e[i*4+2]*inv, e[i*4+3]*inv);
    }
    if (lane == 0) out_idx[r] = (float)bi;
    const float4* vp4 = (const float4*)(g_vp_norm + (long)bi * 256);
    float4* oh4 = (float4*)(out_hard + (long)r * 256);
    oh4[lane*2]     = vp4[lane*2];
    oh4[lane*2 + 1] = vp4[lane*2 + 1];
}

// ============= fp16 mma.sync GEMM with ldmatrix (m16n8k16, sm_80+) =============
// Unified kernel: blockIdx.x < nsCount  -> nonsym tile of C_ns = A_ns @ B_ns^T
//                 blockIdx.x >= nsCount -> symmetric Gram tile (batched, T=1024)
// Block tile 128x128, BK=32, 3-stage cp.async, 8 warps x (64x32), 2 CTAs/SM.
// ACC16: fp16 accumulators per chunk (zero-init), promoted to fp32 each chunk.
__device__ __forceinline__ void cp16(uint32_t saddr, const void* g) {
    asm volatile("cp.async.cg.shared.global [%0], [%1], 16;"
                 :: "r"(saddr), "l"(g) : "memory");
}
__device__ __forceinline__ void ldsm4(uint32_t* r, uint32_t addr) {
    asm volatile("ldmatrix.sync.aligned.m8n8.x4.shared.b16 {%0,%1,%2,%3}, [%4];"
                 : "=r"(r[0]), "=r"(r[1]), "=r"(r[2]), "=r"(r[3]) : "r"(addr));
}
__device__ __forceinline__ void mma16(float* d, const uint32_t* a, const uint32_t* b) {
    asm volatile(
        "mma.sync.aligned.m16n8k16.row.col.f32.f16.f16.f32 "
        "{%0,%1,%2,%3}, {%4,%5,%6,%7}, {%8,%9}, {%0,%1,%2,%3};"
        : "+f"(d[0]), "+f"(d[1]), "+f"(d[2]), "+f"(d[3])
        : "r"(a[0]), "r"(a[1]), "r"(a[2]), "r"(a[3]), "r"(b[0]), "r"(b[1]));
}
__device__ __forceinline__ void mma16h(uint32_t* d, const uint32_t* a, const uint32_t* b) {
    asm volatile(
        "mma.sync.aligned.m16n8k16.row.col.f16.f16.f16.f16 "
        "{%0,%1}, {%2,%3,%4,%5}, {%6,%7}, {%0,%1};"
        : "+r"(d[0]), "+r"(d[1])
        : "r"(a[0]), "r"(a[1]), "r"(a[2]), "r"(a[3]), "r"(b[0]), "r"(b[1]));
}

#define STAGE_B 16384   // bytes per stage (A 8192 + B 8192)

template<bool ACC16>
__global__ __launch_bounds__(256, 2) void gemm_h(
    const __half* __restrict__ A_ns, const __half* __restrict__ B_ns,
    float* __restrict__ C_ns, int K, int ldC, int ntX, int nsCount,
    const __half* __restrict__ A_s, float* __restrict__ C_s)
{
    extern __shared__ uint32_t smu[];
    const int t = threadIdx.x;
    const int wid = t >> 5, lane = t & 31;
    const int g = lane >> 2, q = lane & 3;

    const int x = blockIdx.x;
    const bool sym = (x >= nsCount);
    int bi, bj;
    const __half *Ah, *Bh;
    long csOff = 0;
    if (!sym) {
        bi = x / ntX; bj = x % ntX;
        Ah = A_ns + (long)(bi * 128) * K;
        Bh = B_ns + (long)(bj * 128) * K;
    } else {
        int xs = x - nsCount;
        int bz = xs / 36, u = xs % 36, i = 0;
        while (u >= 8 - i) { u -= 8 - i; i++; }  // 36 pairs, i<=j
        bi = i; bj = i + u;
        const __half* base = A_s + (long)bz * TT * DD;   // K == DD here
        Ah = base + (long)(bi * 128) * K;
        Bh = base + (long)(bj * 128) * K;
        csOff = (long)bz * TT * TT;
    }

    uint32_t smb = (uint32_t)__cvta_generic_to_shared(smu);

    // ---- writer precompute: 4 x 16B cp.async per thread (2 A rows, 2 B rows)
    const int wr = t >> 2, wc = t & 3;                   // row 0..63, chunk 0..3
    const uint32_t wdst = (uint32_t)(wr * 64 + ((wc ^ ((wr >> 1) & 3)) << 4));
    const long  gsrc = (long)wr * K + wc * 8;            // halves
    const long  gstep = (long)64 * K;

    auto issue = [&](int kc, int st) {
        uint32_t sb = smb + (uint32_t)st * STAGE_B;
        const __half* ap = Ah + gsrc + kc * 32;
        const __half* bp = Bh + gsrc + kc * 32;
        cp16(sb + wdst,        ap);
        cp16(sb + wdst + 4096, ap + gstep);
        cp16(sb + 8192 + wdst,        bp);
        cp16(sb + 8192 + wdst + 4096, bp + gstep);
        asm volatile("cp.async.commit_group;" ::: "memory");
    };

    // ---- reader precompute: ldmatrix lane addresses (all lane-constant bases)
    const int mbase = (wid >> 2) * 64, nbase = (wid & 3) * 32;
    const int rA  = (lane & 7) + ((lane >> 3) & 1) * 8;  // row within 16-row tile
    const int cA  = lane >> 4;                           // k-chunk bit
    const int swA = (rA >> 1) & 3;
    const uint32_t laneA = (uint32_t)((mbase + rA) * 64);
    const int rB  = ((lane >> 4) << 3) + (lane & 7);
    const int cB  = (lane >> 3) & 1;
    const int swB = (rB >> 1) & 3;
    const uint32_t laneB = (uint32_t)(8192 + (nbase + rB) * 64);
    const uint32_t koffA0 = (uint32_t)(((0 + cA) ^ swA) << 4);
    const uint32_t koffA1 = (uint32_t)(((2 + cA) ^ swA) << 4);

    float acc[4][4][4];
    #pragma unroll
    for (int mi = 0; mi < 4; mi++)
        #pragma unroll
        for (int ni = 0; ni < 4; ni++)
            #pragma unroll
            for (int j = 0; j < 4; j++) acc[mi][ni][j] = 0.0f;

    const int nk = K >> 5;                // >= 8 here
    issue(0, 0);
    issue(1, 1);

    for (int k = 0; k < nk; k++) {
        int st = k % 3;
        if (k + 1 < nk) asm volatile("cp.async.wait_group 1;" ::: "memory");
        else            asm volatile("cp.async.wait_group 0;" ::: "memory");
        __syncthreads();                   // single sync per iteration
        if (k + 2 < nk) issue(k + 2, (k + 2) % 3);

        uint32_t sb = smb + (uint32_t)st * STAGE_B;
        // load all B fragments for both k-halves
        uint32_t bF[2][4][2];
        #pragma unroll
        for (int ks = 0; ks < 2; ks++) {
            uint32_t koffB = (uint32_t)(((ks * 2 + cB) ^ swB) << 4);
            uint32_t tmp[4];
            ldsm4(tmp, sb + laneB + koffB);
            bF[ks][0][0] = tmp[0]; bF[ks][0][1] = tmp[1];
            bF[ks][1][0] = tmp[2]; bF[ks][1][1] = tmp[3];
            ldsm4(tmp, sb + laneB + 1024 + koffB);
            bF[ks][2][0] = tmp[0]; bF[ks][2][1] = tmp[1];
            bF[ks][3][0] = tmp[2]; bF[ks][3][1] = tmp[3];
        }
        #pragma unroll
        for (int mi = 0; mi < 4; mi++) {
            uint32_t aF[2][4];
            ldsm4(aF[0], sb + laneA + (uint32_t)(mi * 1024) + koffA0);
            ldsm4(aF[1], sb + laneA + (uint32_t)(mi * 1024) + koffA1);
            #pragma unroll
            for (int ni = 0; ni < 4; ni++) {
                if constexpr (ACC16) {
                    uint32_t d2[2] = {0u, 0u};
                    mma16h(d2, aF[0], bF[0][ni]);
                    mma16h(d2, aF[1], bF[1][ni]);
                    __half2 h0 = *(__half2*)&d2[0];
                    __half2 h1 = *(__half2*)&d2[1];
                    float2 f0 = __half22float2(h0);
                    float2 f1 = __half22float2(h1);
                    acc[mi][ni][0] += f0.x; acc[mi][ni][1] += f0.y;
                    acc[mi][ni][2] += f1.x; acc[mi][ni][3] += f1.y;
                } else {
                    mma16(acc[mi][ni], aF[0], bF[0][ni]);
                    mma16(acc[mi][ni], aF[1], bF[1][ni]);
                }
            }
        }
    }

    if (!sym) {
        float* Cp = C_ns + (long)(bi * 128) * ldC + bj * 128;
        #pragma unroll
        for (int mi = 0; mi < 4; mi++) {
            int row = (wid >> 2) * 64 + mi * 16 + g;
            #pragma unroll
            for (int ni = 0; ni < 4; ni++) {
                int col = (wid & 3) * 32 + ni * 8 + q * 2;
                *(float2*)&Cp[(long)row * ldC + col] =
                    make_float2(acc[mi][ni][0], acc[mi][ni][1]);
                *(float2*)&Cp[(long)(row + 8) * ldC + col] =
                    make_float2(acc[mi][ni][2], acc[mi][ni][3]);
            }
        }
    } else {
        __syncthreads();                  // stages done; reuse smem
        float* eb = (float*)smu;          // 128 x 132 staging tile
        #pragma unroll
        for (int mi = 0; mi < 4; mi++) {
            int row = (wid >> 2) * 64 + mi * 16 + g;
            #pragma unroll
            for (int ni = 0; ni < 4; ni++) {
                int col = (wid & 3) * 32 + ni * 8 + q * 2;
                *(float2*)&eb[row * 132 + col] =
                    make_float2(acc[mi][ni][0], acc[mi][ni][1]);
                *(float2*)&eb[(row + 8) * 132 + col] =
                    make_float2(acc[mi][ni][2], acc[mi][ni][3]);
            }
        }
        __syncthreads();
        float* Cn = C_s + csOff + (long)(bi * 128) * TT + bj * 128;
        #pragma unroll
        for (int i2 = 0; i2 < 16; i2++) {
            int id = t + i2 * 256;
            int r = id >> 5, c4 = (id & 31) * 4;
            *(float4*)&Cn[(long)r * TT + c4] = *(float4*)&eb[r * 132 + c4];
        }
        if (bi != bj) {
            float* Cm = C_s + csOff + (long)(bj * 128) * TT + bi * 128;
            #pragma unroll
            for (int i2 = 0; i2 < 16; i2++) {
                int id = t + i2 * 256;
                int rr = id & 127, c4 = (id >> 7) * 4;   // conflict-free map
                float4 v;
                v.x = eb[(c4 + 0) * 132 + rr];
                v.y = eb[(c4 + 1) * 132 + rr];
                v.z = eb[(c4 + 2) * 132 + rr];
                v.w = eb[(c4 + 3) * 132 + rr];
                *(float4*)&Cm[(long)rr * TT + c4] = v;
            }
        }
    }
}

// --------------------------------- launch --------------------------------------
extern "C" void kernel_launch(void* const* d_in, const int* in_sizes, int n_in,
                              void* d_out, int out_size) {
    const float* key_soft = (const float*)d_in[0];   // [16,1024,256]
    const float* keys     = (const float*)d_in[1];   // [512,256]
    const float* vparams  = (const float*)d_in[2];   // [512,256]
    float* out = (float*)d_out;

    float* o_idx  = out;                             // [16384]
    float* o_vw   = o_idx  + MR;                     // [16384,256]
    float* o_hard = o_vw   + (long)MR * DD;          // [16384,256]
    float* o_vpss = o_hard + (long)MR * DD;          // [16,1024,1024]
    float* o_vpsh = o_vpss + (long)MR * TT;          // [16384,512]
    float* o_kss  = o_vpsh + (long)MR * NE;          // [16,1024,1024]
    float* o_ksh  = o_kss  + (long)MR * TT;          // [16384,512]

    __half *p_ksn_h, *p_wh, *p_keys_h, *p_vpn_h, *p_vpnT_h, *p_vwh;
    float *p_ksn_f, *p_keys_f, *p_vpn;
    cudaGetSymbolAddress((void**)&p_ksn_h,  g_ksn_h);
    cudaGetSymbolAddress((void**)&p_ksn_f,  g_ksn_f);
    cudaGetSymbolAddress((void**)&p_wh,     g_wh);
    cudaGetSymbolAddress((void**)&p_keys_h, g_keys_h);
    cudaGetSymbolAddress((void**)&p_keys_f, g_keys_f);
    cudaGetSymbolAddress((void**)&p_vpn,    g_vp_norm);
    cudaGetSymbolAddress((void**)&p_vpn_h,  g_vpn_h);
    cudaGetSymbolAddress((void**)&p_vpnT_h, g_vpnT_h);
    cudaGetSymbolAddress((void**)&p_vwh,    g_vwh);

    const int SMX = 128 * 132 * 4;        // 67584: sym epilogue (>= stage bytes)
    const int S1  = 3 * STAGE_B;          // 49152: stages only (nonsym-only call)
    cudaFuncSetAttribute(gemm_h<true>,
                         cudaFuncAttributeMaxDynamicSharedMemorySize, SMX);
    cudaFuncSetAttribute(gemm_h<false>,
                         cudaFuncAttributeMaxDynamicSharedMemorySize, S1);

    // 1) normalize codebooks + inputs (fp32 + fp16 copies)
    rownorm_hl<<<NE / 16, 256>>>(keys,    p_keys_f, p_keys_h, NE);
    rownorm_hl<<<NE / 16, 256>>>(vparams, p_vpn,    p_vpn_h,  NE);
    transpose_vp<<<dim3(DD / 32, NE / 32), dim3(32, 32)>>>();
    rownorm_hl<<<MR / 16, 256>>>(key_soft, p_ksn_f, p_ksn_h, MR);

    // 2) FUSED: score_ksh (512 nonsym tiles) + score_kss (576 sym tiles), fp16-acc
    gemm_h<true><<<512 + 36 * BB, 256, SMX>>>(
        p_ksn_h, p_keys_h, o_ksh, DD, NE, NE / 128, 512,
        p_ksn_h, o_kss);

    // 3) warp-per-row softmax + exact-argmax correction + hard gather
    softmax_argmax<<<MR / 8, 256>>>(o_ksh, o_idx, o_hard);

    // 4) vw_raw = w @ vp_norm  [16384,256] — fp32-acc (long-K small-increment sum)
    gemm_h<false><<<(DD / 128) * (MR / 128), 256, S1>>>(
        p_wh, p_vpnT_h, o_vw, NE, DD, DD / 128, (DD / 128) * (MR / 128),
        nullptr, nullptr);

    // 5) normalize vparams_w: fp32 in place + fp16 copy
    rownorm_hl<<<MR / 16, 256>>>(o_vw, o_vw, p_vwh, MR);

    // 6) FUSED: score_vpsh (512 nonsym tiles) + score_vpss (576 sym tiles), fp16-acc
    gemm_h<true><<<512 + 36 * BB, 256, SMX>>>(
        p_vwh, p_vpn_h, o_vpsh, DD, NE, NE / 128, 512,
        p_vwh, o_vpss);
}

// round 12
// speedup vs baseline: 5.3889x; 1.0988x over previous
#include <cuda_runtime.h>
#include <cuda_fp16.h>
#include <math.h>
#include <stdint.h>

// Problem dims (fixed by the dataset)
#define BB   16
#define TT   1024
#define DD   256        // key_dim == e_dim
#define NE   512        // codebook size
#define MR   (BB*TT)    // 16384 rows

// ---------------- scratch (__device__ globals: allocation-free) ----------------
__device__ __half g_ksn_h[MR * DD];     // normalized key_soft, fp16
__device__ float  g_ksn_f[MR * DD];     // normalized key_soft, fp32 (argmax check)
__device__ __half g_wh[MR * NE];        // softmax weights fp16
__device__ __half g_keys_h[NE * DD];
__device__ float  g_keys_f[NE * DD];    // fp32 keys_norm (argmax check)
__device__ float  g_vp_norm[NE * DD];   // fp32 (exact gather source)
__device__ __half g_vpn_h[NE * DD];
__device__ __half g_vpnT_h[DD * NE];    // vp_norm transposed fp16 [E, n_e]
__device__ __half g_vwh[MR * DD];       // normalized vparams_w fp16

// =============================== aux kernels ===================================
// L2 normalize, 256 cols, 4 rows per warp (MLP=4); optional fp32 + fp16 outputs
__global__ void rownorm_hl(const float* __restrict__ in, float* __restrict__ of,
                           __half* __restrict__ oh, int nrows) {
    long w = (long)((blockIdx.x * blockDim.x + threadIdx.x) >> 5) * 4;
    int lane = threadIdx.x & 31;
    if (w >= nrows) return;
    float4 v[4][2];
    #pragma unroll
    for (int rr = 0; rr < 4; rr++) {
        const float4* ip = (const float4*)(in + (w + rr) * 256);
        v[rr][0] = ip[lane]; v[rr][1] = ip[lane + 32];
    }
    float s[4];
    #pragma unroll
    for (int rr = 0; rr < 4; rr++) {
        float4 a = v[rr][0], b = v[rr][1];
        s[rr] = a.x*a.x + a.y*a.y + a.z*a.z + a.w*a.w
              + b.x*b.x + b.y*b.y + b.z*b.z + b.w*b.w;
    }
    #pragma unroll
    for (int o = 16; o; o >>= 1) {
        #pragma unroll
        for (int rr = 0; rr < 4; rr++)
            s[rr] += __shfl_xor_sync(0xffffffffu, s[rr], o);
    }
    #pragma unroll
    for (int rr = 0; rr < 4; rr++) {
        float k = 1.0f / fmaxf(sqrtf(s[rr]), 1e-12f);
        float4 a = v[rr][0], b = v[rr][1];
        float4 r0 = make_float4(a.x*k, a.y*k, a.z*k, a.w*k);
        float4 r1 = make_float4(b.x*k, b.y*k, b.z*k, b.w*k);
        if (of) {
            float4* op = (float4*)(of + (w + rr) * 256);
            op[lane] = r0; op[lane + 32] = r1;
        }
        __half2* hp = (__half2*)(oh + (w + rr) * 256);
        hp[lane*2]        = __floats2half2_rn(r0.x, r0.y);
        hp[lane*2+1]      = __floats2half2_rn(r0.z, r0.w);
        hp[64 + lane*2]   = __floats2half2_rn(r1.x, r1.y);
        hp[64 + lane*2+1] = __floats2half2_rn(r1.z, r1.w);
    }
}

__global__ void transpose_vp() {
    __shared__ float tile[32][33];
    int x = blockIdx.x * 32 + threadIdx.x;
    int y = blockIdx.y * 32 + threadIdx.y;
    tile[threadIdx.y][threadIdx.x] = g_vp_norm[y * 256 + x];
    __syncthreads();
    int tx = blockIdx.y * 32 + threadIdx.x;
    int ty = blockIdx.x * 32 + threadIdx.y;
    g_vpnT_h[ty * 512 + tx] = __float2half_rn(tile[threadIdx.x][threadIdx.y]);
}

// warp-per-row softmax + exact-argmax (fp32 candidate re-check) + hard gather
__global__ void softmax_argmax(const float* __restrict__ ksh,
                               float* __restrict__ out_idx,
                               float* __restrict__ out_hard) {
    int r = (blockIdx.x * blockDim.x + threadIdx.x) >> 5;
    int lane = threadIdx.x & 31;
    if (r >= MR) return;
    const float4* row4 = (const float4*)(ksh + (long)r * NE);
    float4 v[4];
    #pragma unroll
    for (int i = 0; i < 4; i++) v[i] = row4[i * 32 + lane];
    // warp max
    float m = -2e30f;
    #pragma unroll
    for (int i = 0; i < 4; i++)
        m = fmaxf(m, fmaxf(fmaxf(v[i].x, v[i].y), fmaxf(v[i].z, v[i].w)));
    #pragma unroll
    for (int o = 16; o; o >>= 1) m = fmaxf(m, __shfl_xor_sync(0xffffffffu, m, o));

    // fp32 query row (for exact re-check)
    const float4* xr4 = (const float4*)(g_ksn_f + (long)r * 256);
    float4 x0 = xr4[lane * 2], x1 = xr4[lane * 2 + 1];

    // candidate mask: fp16 dot error (input rounding + fp16-acc chain) << eps
    const float eps = 8e-3f;
    unsigned pend = 0;
    #pragma unroll
    for (int i = 0; i < 4; i++) {
        if (v[i].x >= m - eps) pend |= 1u << (i * 4 + 0);
        if (v[i].y >= m - eps) pend |= 1u << (i * 4 + 1);
        if (v[i].z >= m - eps) pend |= 1u << (i * 4 + 2);
        if (v[i].w >= m - eps) pend |= 1u << (i * 4 + 3);
    }
    float bv = -2e30f; int bi = 1 << 30;
    while (true) {
        unsigned act = __ballot_sync(0xffffffffu, pend != 0);
        if (!act) break;
        int leader = __ffs(act) - 1;
        int slot = (pend ? __ffs(pend) - 1 : 0);
        slot = __shfl_sync(0xffffffffu, slot, leader);
        int j = (slot >> 2) * 128 + leader * 4 + (slot & 3);
        const float4* kp = (const float4*)(g_keys_f + (long)j * 256);
        float4 u0 = kp[lane * 2], u1 = kp[lane * 2 + 1];
        float d = u0.x*x0.x + u0.y*x0.y + u0.z*x0.z + u0.w*x0.w
                + u1.x*x1.x + u1.y*x1.y + u1.z*x1.z + u1.w*x1.w;
        #pragma unroll
        for (int o = 16; o; o >>= 1) d += __shfl_xor_sync(0xffffffffu, d, o);
        if (d > bv || (d == bv && j < bi)) { bv = d; bi = j; }
        if (lane == leader) pend &= pend - 1;
    }

    // softmax (fp16-accurate scores: fine for w)
    float e[16];
    float sum = 0.0f;
    #pragma unroll
    for (int i = 0; i < 4; i++) {
        e[i*4+0] = expf(v[i].x - m); e[i*4+1] = expf(v[i].y - m);
        e[i*4+2] = expf(v[i].z - m); e[i*4+3] = expf(v[i].w - m);
        sum += e[i*4+0] + e[i*4+1] + e[i*4+2] + e[i*4+3];
    }
    #pragma unroll
    for (int o = 16; o; o >>= 1) sum += __shfl_xor_sync(0xffffffffu, sum, o);
    float inv = 1.0f / sum;
    __half2* wp = (__half2*)(g_wh + (long)r * NE);
    #pragma unroll
    for (int i = 0; i < 4; i++) {
        wp[i*64 + lane*2]     = __floats2half2_rn(e[i*4+0]*inv, e[i*4+1]*inv);
        wp[i*64 + lane*2 + 1] = __floats2half2_rn(e[i*4+2]*inv, e[i*4+3]*inv);
    }
    if (lane == 0) out_idx[r] = (float)bi;
    const float4* vp4 = (const float4*)(g_vp_norm + (long)bi * 256);
    float4* oh4 = (float4*)(out_hard + (long)r * 256);
    oh4[lane*2]     = vp4[lane*2];
    oh4[lane*2 + 1] = vp4[lane*2 + 1];
}

// ============= fp16 mma.sync GEMM with ldmatrix (m16n8k16, sm_80+) =============
// Unified kernel: blockIdx.x < nsCount  -> nonsym tile of C_ns = A_ns @ B_ns^T
//                 blockIdx.x >= nsCount -> symmetric Gram tile (batched, T=1024)
// Block tile 128x128, BK=32, 3-stage cp.async, 8 warps x (64x32), 2 CTAs/SM.
// ACC16: fp16 accumulators chained across the WHOLE k-loop; single promotion
// to fp32 in the epilogue (no per-chunk cvt/add traffic).
__device__ __forceinline__ void cp16(uint32_t saddr, const void* g) {
    asm volatile("cp.async.cg.shared.global [%0], [%1], 16;"
                 :: "r"(saddr), "l"(g) : "memory");
}
__device__ __forceinline__ void ldsm4(uint32_t* r, uint32_t addr) {
    asm volatile("ldmatrix.sync.aligned.m8n8.x4.shared.b16 {%0,%1,%2,%3}, [%4];"
                 : "=r"(r[0]), "=r"(r[1]), "=r"(r[2]), "=r"(r[3]) : "r"(addr));
}
__device__ __forceinline__ void mma16(float* d, const uint32_t* a, const uint32_t* b) {
    asm volatile(
        "mma.sync.aligned.m16n8k16.row.col.f32.f16.f16.f32 "
        "{%0,%1,%2,%3}, {%4,%5,%6,%7}, {%8,%9}, {%0,%1,%2,%3};"
        : "+f"(d[0]), "+f"(d[1]), "+f"(d[2]), "+f"(d[3])
        : "r"(a[0]), "r"(a[1]), "r"(a[2]), "r"(a[3]), "r"(b[0]), "r"(b[1]));
}
__device__ __forceinline__ void mma16h(uint32_t* d, const uint32_t* a, const uint32_t* b) {
    asm volatile(
        "mma.sync.aligned.m16n8k16.row.col.f16.f16.f16.f16 "
        "{%0,%1}, {%2,%3,%4,%5}, {%6,%7}, {%0,%1};"
        : "+r"(d[0]), "+r"(d[1])
        : "r"(a[0]), "r"(a[1]), "r"(a[2]), "r"(a[3]), "r"(b[0]), "r"(b[1]));
}

#define STAGE_B 16384   // bytes per stage (A 8192 + B 8192)

template<bool ACC16>
__global__ __launch_bounds__(256, 2) void gemm_h(
    const __half* __restrict__ A_ns, const __half* __restrict__ B_ns,
    float* __restrict__ C_ns, int K, int ldC, int ntX, int nsCount,
    const __half* __restrict__ A_s, float* __restrict__ C_s)
{
    extern __shared__ uint32_t smu[];
    const int t = threadIdx.x;
    const int wid = t >> 5, lane = t & 31;
    const int g = lane >> 2, q = lane & 3;

    const int x = blockIdx.x;
    const bool sym = (x >= nsCount);
    int bi, bj;
    const __half *Ah, *Bh;
    long csOff = 0;
    if (!sym) {
        bi = x / ntX; bj = x % ntX;
        Ah = A_ns + (long)(bi * 128) * K;
        Bh = B_ns + (long)(bj * 128) * K;
    } else {
        int xs = x - nsCount;
        int bz = xs / 36, u = xs % 36, i = 0;
        while (u >= 8 - i) { u -= 8 - i; i++; }  // 36 pairs, i<=j
        bi = i; bj = i + u;
        const __half* base = A_s + (long)bz * TT * DD;   // K == DD here
        Ah = base + (long)(bi * 128) * K;
        Bh = base + (long)(bj * 128) * K;
        csOff = (long)bz * TT * TT;
    }

    uint32_t smb = (uint32_t)__cvta_generic_to_shared(smu);

    // ---- writer precompute: 4 x 16B cp.async per thread (2 A rows, 2 B rows)
    const int wr = t >> 2, wc = t & 3;                   // row 0..63, chunk 0..3
    const uint32_t wdst = (uint32_t)(wr * 64 + ((wc ^ ((wr >> 1) & 3)) << 4));
    const long  gsrc = (long)wr * K + wc * 8;            // halves
    const long  gstep = (long)64 * K;

    auto issue = [&](int kc, int st) {
        uint32_t sb = smb + (uint32_t)st * STAGE_B;
        const __half* ap = Ah + gsrc + kc * 32;
        const __half* bp = Bh + gsrc + kc * 32;
        cp16(sb + wdst,        ap);
        cp16(sb + wdst + 4096, ap + gstep);
        cp16(sb + 8192 + wdst,        bp);
        cp16(sb + 8192 + wdst + 4096, bp + gstep);
        asm volatile("cp.async.commit_group;" ::: "memory");
    };

    // ---- reader precompute: ldmatrix lane addresses (all lane-constant bases)
    const int mbase = (wid >> 2) * 64, nbase = (wid & 3) * 32;
    const int rA  = (lane & 7) + ((lane >> 3) & 1) * 8;  // row within 16-row tile
    const int cA  = lane >> 4;                           // k-chunk bit
    const int swA = (rA >> 1) & 3;
    const uint32_t laneA = (uint32_t)((mbase + rA) * 64);
    const int rB  = ((lane >> 4) << 3) + (lane & 7);
    const int cB  = (lane >> 3) & 1;
    const int swB = (rB >> 1) & 3;
    const uint32_t laneB = (uint32_t)(8192 + (nbase + rB) * 64);
    const uint32_t koffA0 = (uint32_t)(((0 + cA) ^ swA) << 4);
    const uint32_t koffA1 = (uint32_t)(((2 + cA) ^ swA) << 4);

    float    accf[4][4][4];
    uint32_t acch[4][4][2];
    if constexpr (ACC16) {
        #pragma unroll
        for (int mi = 0; mi < 4; mi++)
            #pragma unroll
            for (int ni = 0; ni < 4; ni++) { acch[mi][ni][0] = 0u; acch[mi][ni][1] = 0u; }
    } else {
        #pragma unroll
        for (int mi = 0; mi < 4; mi++)
            #pragma unroll
            for (int ni = 0; ni < 4; ni++)
                #pragma unroll
                for (int j = 0; j < 4; j++) accf[mi][ni][j] = 0.0f;
    }

    const int nk = K >> 5;                // >= 8 here
    issue(0, 0);
    issue(1, 1);

    for (int k = 0; k < nk; k++) {
        int st = k % 3;
        if (k + 1 < nk) asm volatile("cp.async.wait_group 1;" ::: "memory");
        else            asm volatile("cp.async.wait_group 0;" ::: "memory");
        __syncthreads();                   // single sync per iteration
        if (k + 2 < nk) issue(k + 2, (k + 2) % 3);

        uint32_t sb = smb + (uint32_t)st * STAGE_B;
        uint32_t bF[2][4][2];
        #pragma unroll
        for (int ks = 0; ks < 2; ks++) {
            uint32_t koffB = (uint32_t)(((ks * 2 + cB) ^ swB) << 4);
            uint32_t tmp[4];
            ldsm4(tmp, sb + laneB + koffB);
            bF[ks][0][0] = tmp[0]; bF[ks][0][1] = tmp[1];
            bF[ks][1][0] = tmp[2]; bF[ks][1][1] = tmp[3];
            ldsm4(tmp, sb + laneB + 1024 + koffB);
            bF[ks][2][0] = tmp[0]; bF[ks][2][1] = tmp[1];
            bF[ks][3][0] = tmp[2]; bF[ks][3][1] = tmp[3];
        }
        #pragma unroll
        for (int mi = 0; mi < 4; mi++) {
            uint32_t aF[2][4];
            ldsm4(aF[0], sb + laneA + (uint32_t)(mi * 1024) + koffA0);
            ldsm4(aF[1], sb + laneA + (uint32_t)(mi * 1024) + koffA1);
            #pragma unroll
            for (int ni = 0; ni < 4; ni++) {
                if constexpr (ACC16) {
                    mma16h(acch[mi][ni], aF[0], bF[0][ni]);
                    mma16h(acch[mi][ni], aF[1], bF[1][ni]);
                } else {
                    mma16(accf[mi][ni], aF[0], bF[0][ni]);
                    mma16(accf[mi][ni], aF[1], bF[1][ni]);
                }
            }
        }
    }

    // extract tile (mi,ni) accumulator as 4 floats (single promotion for ACC16)
    auto getc = [&](int mi, int ni, float* c) {
        if constexpr (ACC16) {
            float2 f0 = __half22float2(*(__half2*)&acch[mi][ni][0]);
            float2 f1 = __half22float2(*(__half2*)&acch[mi][ni][1]);
            c[0] = f0.x; c[1] = f0.y; c[2] = f1.x; c[3] = f1.y;
        } else {
            c[0] = accf[mi][ni][0]; c[1] = accf[mi][ni][1];
            c[2] = accf[mi][ni][2]; c[3] = accf[mi][ni][3];
        }
    };

    if (!sym) {
        float* Cp = C_ns + (long)(bi * 128) * ldC + bj * 128;
        #pragma unroll
        for (int mi = 0; mi < 4; mi++) {
            int row = (wid >> 2) * 64 + mi * 16 + g;
            #pragma unroll
            for (int ni = 0; ni < 4; ni++) {
                int col = (wid & 3) * 32 + ni * 8 + q * 2;
                float c[4]; getc(mi, ni, c);
                *(float2*)&Cp[(long)row * ldC + col]       = make_float2(c[0], c[1]);
                *(float2*)&Cp[(long)(row + 8) * ldC + col] = make_float2(c[2], c[3]);
            }
        }
    } else {
        __syncthreads();                  // stages done; reuse smem
        float* eb = (float*)smu;          // 128 x 132 staging tile
        #pragma unroll
        for (int mi = 0; mi < 4; mi++) {
            int row = (wid >> 2) * 64 + mi * 16 + g;
            #pragma unroll
            for (int ni = 0; ni < 4; ni++) {
                int col = (wid & 3) * 32 + ni * 8 + q * 2;
                float c[4]; getc(mi, ni, c);
                *(float2*)&eb[row * 132 + col]       = make_float2(c[0], c[1]);
                *(float2*)&eb[(row + 8) * 132 + col] = make_float2(c[2], c[3]);
            }
        }
        __syncthreads();
        float* Cn = C_s + csOff + (long)(bi * 128) * TT + bj * 128;
        #pragma unroll
        for (int i2 = 0; i2 < 16; i2++) {
            int id = t + i2 * 256;
            int r = id >> 5, c4 = (id & 31) * 4;
            *(float4*)&Cn[(long)r * TT + c4] = *(float4*)&eb[r * 132 + c4];
        }
        if (bi != bj) {
            float* Cm = C_s + csOff + (long)(bj * 128) * TT + bi * 128;
            #pragma unroll
            for (int i2 = 0; i2 < 16; i2++) {
                int id = t + i2 * 256;
                int rr = id & 127, c4 = (id >> 7) * 4;   // conflict-free map
                float4 v;
                v.x = eb[(c4 + 0) * 132 + rr];
                v.y = eb[(c4 + 1) * 132 + rr];
                v.z = eb[(c4 + 2) * 132 + rr];
                v.w = eb[(c4 + 3) * 132 + rr];
                *(float4*)&Cm[(long)rr * TT + c4] = v;
            }
        }
    }
}

// --------------------------------- launch --------------------------------------
extern "C" void kernel_launch(void* const* d_in, const int* in_sizes, int n_in,
                              void* d_out, int out_size) {
    const float* key_soft = (const float*)d_in[0];   // [16,1024,256]
    const float* keys     = (const float*)d_in[1];   // [512,256]
    const float* vparams  = (const float*)d_in[2];   // [512,256]
    float* out = (float*)d_out;

    float* o_idx  = out;                             // [16384]
    float* o_vw   = o_idx  + MR;                     // [16384,256]
    float* o_hard = o_vw   + (long)MR * DD;          // [16384,256]
    float* o_vpss = o_hard + (long)MR * DD;          // [16,1024,1024]
    float* o_vpsh = o_vpss + (long)MR * TT;          // [16384,512]
    float* o_kss  = o_vpsh + (long)MR * NE;          // [16,1024,1024]
    float* o_ksh  = o_kss  + (long)MR * TT;          // [16384,512]

    __half *p_ksn_h, *p_wh, *p_keys_h, *p_vpn_h, *p_vpnT_h, *p_vwh;
    float *p_ksn_f, *p_keys_f, *p_vpn;
    cudaGetSymbolAddress((void**)&p_ksn_h,  g_ksn_h);
    cudaGetSymbolAddress((void**)&p_ksn_f,  g_ksn_f);
    cudaGetSymbolAddress((void**)&p_wh,     g_wh);
    cudaGetSymbolAddress((void**)&p_keys_h, g_keys_h);
    cudaGetSymbolAddress((void**)&p_keys_f, g_keys_f);
    cudaGetSymbolAddress((void**)&p_vpn,    g_vp_norm);
    cudaGetSymbolAddress((void**)&p_vpn_h,  g_vpn_h);
    cudaGetSymbolAddress((void**)&p_vpnT_h, g_vpnT_h);
    cudaGetSymbolAddress((void**)&p_vwh,    g_vwh);

    const int SMX = 128 * 132 * 4;        // 67584: sym epilogue (>= stage bytes)
    const int S1  = 3 * STAGE_B;          // 49152: stages only (nonsym-only call)
    cudaFuncSetAttribute(gemm_h<true>,
                         cudaFuncAttributeMaxDynamicSharedMemorySize, SMX);
    cudaFuncSetAttribute(gemm_h<false>,
                         cudaFuncAttributeMaxDynamicSharedMemorySize, S1);

    // 1) normalize codebooks + inputs (fp32 + fp16 copies)
    rownorm_hl<<<NE / 32, 256>>>(keys,    p_keys_f, p_keys_h, NE);
    rownorm_hl<<<NE / 32, 256>>>(vparams, p_vpn,    p_vpn_h,  NE);
    transpose_vp<<<dim3(DD / 32, NE / 32), dim3(32, 32)>>>();
    rownorm_hl<<<MR / 32, 256>>>(key_soft, p_ksn_f, p_ksn_h, MR);

    // 2) FUSED: score_ksh (512 nonsym tiles) + score_kss (576 sym tiles), fp16-acc
    gemm_h<true><<<512 + 36 * BB, 256, SMX>>>(
        p_ksn_h, p_keys_h, o_ksh, DD, NE, NE / 128, 512,
        p_ksn_h, o_kss);

    // 3) warp-per-row softmax + exact-argmax correction + hard gather
    softmax_argmax<<<MR / 8, 256>>>(o_ksh, o_idx, o_hard);

    // 4) vw_raw = w @ vp_norm  [16384,256] — fp32-acc (long-K small-increment sum)
    gemm_h<false><<<(DD / 128) * (MR / 128), 256, S1>>>(
        p_wh, p_vpnT_h, o_vw, NE, DD, DD / 128, (DD / 128) * (MR / 128),
        nullptr, nullptr);

    // 5) normalize vparams_w: fp32 in place + fp16 copy
    rownorm_hl<<<MR / 32, 256>>>(o_vw, o_vw, p_vwh, MR);

    // 6) FUSED: score_vpsh (512 nonsym tiles) + score_vpss (576 sym tiles), fp16-acc
    gemm_h<true><<<512 + 36 * BB, 256, SMX>>>(
        p_vwh, p_vpn_h, o_vpsh, DD, NE, NE / 128, 512,
        p_vwh, o_vpss);
}